// round 13
// baseline (speedup 1.0000x reference)
#include <cuda_runtime.h>
#include <cuda.h>
#include <dlfcn.h>
#include <cstdint>
#include <cstddef>
#include <cstring>

#define TOKENS 1024
#define HIDDEN 2048
#define INTER  4096
#define NEXP   8
#define NTH    256
#define BK     32
#define TILE_BYTES 16384
#define STG_BYTES  65536                  // A0+A1+B0+B1 per stage (BM=256, BN=256)
#define DYN_SMEM   (2 * STG_BYTES + 1024) // 2 stages, 1 CTA/SM (TMA path)
#define FB_SMEM    (6 * TILE_BYTES + 1024) // fallback path: 2 CTAs/SM
// Compensation for HW fp32->tf32 truncation of B (mean bias ~2^-11 toward zero)
#define SCALE 1.00048828125f

#if defined(__CUDA_ARCH__) && defined(__CUDA_ARCH_FEAT_SM103_ALL)
#define USE_TC 1
#else
#define USE_TC 0
#endif

// ---------------- device scratch ----------------
__device__ int   g_count[NEXP];
__device__ int   g_tok[NEXP][TOKENS];
__device__ float g_w[NEXP][TOKENS];
__device__ float g_xg[(size_t)NEXP * TOKENS * HIDDEN];   // gathered + tf32-rounded X
__device__ float g_act[(size_t)NEXP * TOKENS * INTER];   // tf32-rounded activations

// ---------------- common helpers ----------------
__device__ __forceinline__ uint32_t f2tf32(float f) {
    uint32_t u;
    asm("cvt.rna.tf32.f32 %0, %1;" : "=r"(u) : "f"(f));
    return u;
}
__device__ __forceinline__ float rtf(float f) { return __uint_as_float(f2tf32(f)); }
__device__ __forceinline__ uint32_t smem_u32(const void* p) {
    uint32_t a;
    asm("{ .reg .u64 t; cvta.to.shared.u64 t, %1; cvt.u32.u64 %0, t; }" : "=r"(a) : "l"(p));
    return a;
}
__device__ __forceinline__ void cp16(uint32_t dst, const float* src) {
    asm volatile("cp.async.cg.shared.global [%0], [%1], 16;\n" :: "r"(dst), "l"(src));
}
__device__ __forceinline__ void cp_commit() { asm volatile("cp.async.commit_group;\n"); }
template <int N> __device__ __forceinline__ void cp_wait() {
    asm volatile("cp.async.wait_group %0;\n" :: "n"(N) : "memory");
}

// ---------------- kernel 0: zero out + counts ----------------
__global__ void zero_kernel(float* __restrict__ out) {
    int i = blockIdx.x * blockDim.x + threadIdx.x;
    reinterpret_cast<float4*>(out)[i] = make_float4(0.f, 0.f, 0.f, 0.f);
    if (blockIdx.x == 0 && threadIdx.x < NEXP) g_count[threadIdx.x] = 0;
}

// ---------------- kernel 1: router ----------------
__global__ void router_kernel(const float* __restrict__ logits) {
    int t = blockIdx.x * blockDim.x + threadIdx.x;
    if (t >= TOKENS) return;
    float l[NEXP];
#pragma unroll
    for (int j = 0; j < NEXP; j++) l[j] = logits[t * NEXP + j];
    int i0 = 0;
#pragma unroll
    for (int j = 1; j < NEXP; j++) if (l[j] > l[i0]) i0 = j;
    int i1 = -1;
#pragma unroll
    for (int j = 0; j < NEXP; j++) {
        if (j == i0) continue;
        if (i1 < 0 || l[j] > l[i1]) i1 = j;
    }
    float e1 = __expf(l[i1] - l[i0]);
    float w1 = e1 / (1.f + e1);
    float w0 = 1.f / (1.f + e1);
    int p0 = atomicAdd(&g_count[i0], 1);
    g_tok[i0][p0] = t;  g_w[i0][p0] = w0;
    int p1 = atomicAdd(&g_count[i1], 1);
    g_tok[i1][p1] = t;  g_w[i1][p1] = w1;
}

// ---------------- kernel 2: gather + tf32-round X ----------------
__global__ void gather_kernel(const float* __restrict__ X) {
    int row = blockIdx.x, e = blockIdx.y;
    if (row >= g_count[e]) return;
    int tok = g_tok[e][row];
    const float4* src = reinterpret_cast<const float4*>(X + (size_t)tok * HIDDEN);
    float4* dst = reinterpret_cast<float4*>(g_xg + ((size_t)e * TOKENS + row) * HIDDEN);
#pragma unroll
    for (int j = 0; j < 2; j++) {
        float4 v = src[threadIdx.x + 256 * j];
        v.x = rtf(v.x); v.y = rtf(v.y); v.z = rtf(v.z); v.w = rtf(v.w);
        dst[threadIdx.x + 256 * j] = v;
    }
}

#if USE_TC
// =================================================================
// tcgen05 helpers
// =================================================================
#define MMA_IDESC ((1u<<4)|(2u<<7)|(2u<<10)|((128u/8)<<17)|((128u/16)<<24))

__device__ __forceinline__ uint32_t elect_one() {
    uint32_t p;
    asm volatile("{\n\t.reg .pred p;\n\telect.sync _|p, 0xFFFFFFFF;\n\tselp.b32 %0, 1, 0, p;\n\t}" : "=r"(p));
    return p;
}
__device__ __forceinline__ uint32_t swz(uint32_t o) { return o ^ ((o >> 3) & 0x70); }

static constexpr uint64_t DESC_SW128 =
    (2ull << 61) | (1ull << 46) | (64ull << 32) | (1ull << 16);
__device__ __forceinline__ uint64_t mkdesc(uint32_t addr) {
    return DESC_SW128 | ((uint64_t)(addr >> 4) & 0x3FFF);
}
__device__ __forceinline__ void mma_ss_tf32(uint32_t d, uint64_t ad, uint64_t bd,
                                            uint32_t idesc, bool en) {
    uint32_t e = en ? 1u : 0u;
    asm volatile(
        "{\n\t.reg .pred p;\n\tsetp.ne.u32 p, %4, 0;\n\t"
        "tcgen05.mma.cta_group::1.kind::tf32 [%0], %1, %2, %3, p;\n\t}"
        :: "r"(d), "l"(ad), "l"(bd), "r"(idesc), "r"(e) : "memory");
}
#define MBAR_INIT(a, c)  asm volatile("mbarrier.init.shared.b64 [%0], %1;" :: "r"(a), "r"(c) : "memory")
#define MBAR_EXPECT_TX(a, n) asm volatile("mbarrier.arrive.expect_tx.shared.b64 _, [%0], %1;" :: "r"(a), "r"(n) : "memory")
#define TC_COMMIT(a)     asm volatile("tcgen05.commit.cta_group::1.mbarrier::arrive::one.shared::cluster.b64 [%0];" :: "r"(a) : "memory")
#define TC_ALLOC(a, n)   asm volatile("tcgen05.alloc.cta_group::1.sync.aligned.shared::cta.b32 [%0], %1;" :: "r"(a), "r"(n) : "memory")
#define TC_RELINQ()      asm volatile("tcgen05.relinquish_alloc_permit.cta_group::1.sync.aligned;")
#define TC_DEALLOC(t, n) asm volatile("tcgen05.dealloc.cta_group::1.sync.aligned.b32 %0, %1;" :: "r"(t), "r"(n))
#define TC_WAIT_LD()     asm volatile("tcgen05.wait::ld.sync.aligned;" ::: "memory")
#define TC_FENCE_AFTER() asm volatile("tcgen05.fence::after_thread_sync;" ::: "memory")
#define FENCE_ASYNC()    asm volatile("fence.proxy.async.shared::cta;" ::: "memory")
#define MBAR_WAIT(mbar, par) do {                                              \
    uint32_t _m = (mbar), _p = (par);                                          \
    asm volatile(                                                              \
        "{\n\t.reg .pred P1;\n\t"                                             \
        "WL_%=:\n\t"                                                          \
        "mbarrier.try_wait.parity.acquire.cta.shared::cta.b64 P1, [%0], %1, 0x989680;\n\t" \
        "@P1 bra.uni WD_%=;\n\t"                                              \
        "bra.uni WL_%=;\n\t"                                                  \
        "WD_%=:\n\t}"                                                         \
        :: "r"(_m), "r"(_p) : "memory");                                       \
} while (0)
#define TC_LD_X32(r, a)                                                        \
    asm volatile("tcgen05.ld.sync.aligned.32x32b.x32.b32 "                     \
        "{%0,%1,%2,%3,%4,%5,%6,%7,%8,%9,%10,%11,%12,%13,%14,%15,"              \
        "%16,%17,%18,%19,%20,%21,%22,%23,%24,%25,%26,%27,%28,%29,%30,%31}, [%32];" \
        : "=r"((r)[0]),"=r"((r)[1]),"=r"((r)[2]),"=r"((r)[3]),                  \
          "=r"((r)[4]),"=r"((r)[5]),"=r"((r)[6]),"=r"((r)[7]),                  \
          "=r"((r)[8]),"=r"((r)[9]),"=r"((r)[10]),"=r"((r)[11]),                \
          "=r"((r)[12]),"=r"((r)[13]),"=r"((r)[14]),"=r"((r)[15]),              \
          "=r"((r)[16]),"=r"((r)[17]),"=r"((r)[18]),"=r"((r)[19]),              \
          "=r"((r)[20]),"=r"((r)[21]),"=r"((r)[22]),"=r"((r)[23]),              \
          "=r"((r)[24]),"=r"((r)[25]),"=r"((r)[26]),"=r"((r)[27]),              \
          "=r"((r)[28]),"=r"((r)[29]),"=r"((r)[30]),"=r"((r)[31])               \
        : "r"(a))

__device__ __forceinline__ void tma2d(uint32_t smem, const void* tmap,
                                      int x, int y, uint32_t mbar) {
    asm volatile(
        "cp.async.bulk.tensor.2d.shared::cta.global.tile.mbarrier::complete_tx::bytes "
        "[%0], [%1, {%2, %3}], [%4];"
        :: "r"(smem), "l"(tmap), "r"(x), "r"(y), "r"(mbar) : "memory");
}

// =================================================================
// TMA GEMMs, BM=256 x BN=256 (traffic-optimal under 512-col TMEM).
// Stage = A0+A1+B0+B1 (64KB), 2 stages, 1 CTA/SM, single-thread
// producer+MMA, 16 MMAs/stage. At the LTS cap the stage period is
// TMA-service-bound, so the wait-on-committed-MMA before refill is
// not the binder.
// =================================================================
__global__ void __launch_bounds__(NTH, 1)
gemm1_tma_kernel(const __grid_constant__ CUtensorMap mapA,
                 const __grid_constant__ CUtensorMap mapB) {
    const int e = blockIdx.z;
    const int ne = g_count[e];
    const int row0 = blockIdx.y * 256;
    if (row0 >= ne) return;
    const int col0 = blockIdx.x * 128;   // 128 gate + 128 up cols
    const bool use2 = (row0 + 128) < ne;

    extern __shared__ char dynsm[];
    __shared__ uint32_t s_tmem;
    __shared__ __align__(8) uint64_t s_full[2], s_mma[2];

    char* sm_c = (char*)(((uintptr_t)dynsm + 1023) & ~(uintptr_t)1023);
    const uint32_t sm_u = smem_u32(sm_c);

    const int tid = threadIdx.x, warp = tid >> 5, lane = tid & 31;
    if (tid < 2) MBAR_INIT(smem_u32(&s_full[tid]), 1);
    else if (tid < 4) MBAR_INIT(smem_u32(&s_mma[tid - 2]), 1);
    if (warp == 0) { TC_ALLOC(smem_u32(&s_tmem), 512); TC_RELINQ(); }
    __syncthreads();
    const uint32_t tmem = s_tmem;
    // TMEM layout: [0]=blk0 gate, [128]=blk0 up, [256]=blk1 gate, [384]=blk1 up

    const int aY0 = e * TOKENS + row0;
    const int aY1 = aY0 + 128;
    const int bYg = e * (2 * INTER) + col0;
    const int bYu = e * (2 * INTER) + INTER + col0;

    if (warp == 0 && elect_one()) {
        uint32_t fullu[2], mmau[2];
#pragma unroll
        for (int i = 0; i < 2; i++) { fullu[i] = smem_u32(&s_full[i]); mmau[i] = smem_u32(&s_mma[i]); }

        auto fill = [&](int st) {
            int sl = st & 1;
            uint32_t base = sm_u + sl * STG_BYTES;
            MBAR_EXPECT_TX(fullu[sl], STG_BYTES);
            tma2d(base,                  &mapA, st * BK, aY0, fullu[sl]);
            tma2d(base + TILE_BYTES,     &mapA, st * BK, aY1, fullu[sl]);
            tma2d(base + 2 * TILE_BYTES, &mapB, st * BK, bYg, fullu[sl]);
            tma2d(base + 3 * TILE_BYTES, &mapB, st * BK, bYu, fullu[sl]);
        };

        fill(0); fill(1);
        const int NS = HIDDEN / BK;  // 64
        for (int s = 0; s < NS; s++) {
            MBAR_WAIT(fullu[s & 1], (s >> 1) & 1);
            uint32_t base = sm_u + (s & 1) * STG_BYTES;
            uint64_t a0 = mkdesc(base);
            uint64_t a1 = mkdesc(base + TILE_BYTES);
            uint64_t bg = mkdesc(base + 2 * TILE_BYTES);
            uint64_t bu = mkdesc(base + 3 * TILE_BYTES);
            bool en0 = !(s == 0);
#pragma unroll
            for (int k = 0; k < 4; k++) {
                bool en = en0 || k > 0;
                mma_ss_tf32(tmem,       a0 + 2 * k, bg + 2 * k, MMA_IDESC, en);
                mma_ss_tf32(tmem + 128, a0 + 2 * k, bu + 2 * k, MMA_IDESC, en);
                if (use2) {
                    mma_ss_tf32(tmem + 256, a1 + 2 * k, bg + 2 * k, MMA_IDESC, en);
                    mma_ss_tf32(tmem + 384, a1 + 2 * k, bu + 2 * k, MMA_IDESC, en);
                }
            }
            TC_COMMIT(mmau[s & 1]);
            if (s + 2 < NS) {
                MBAR_WAIT(mmau[s & 1], (s >> 1) & 1);
                fill(s + 2);
            }
        }
        MBAR_WAIT(mmau[(NS - 1) & 1], ((NS - 1) >> 1) & 1);
    }
    __syncthreads();
    TC_FENCE_AFTER();

    // epilogue: act = silu(g*SCALE)*(u*SCALE); per row-block, 2x 32-col passes/warp
    {
        const int sub = warp & 3, half = warp >> 2;
        const int nblk = use2 ? 2 : 1;
        for (int blk = 0; blk < nblk; blk++) {
            const int slot = row0 + blk * 128 + sub * 32 + lane;
            float* dstb = (slot < ne)
                ? g_act + ((size_t)e * TOKENS + slot) * INTER + col0 : nullptr;
#pragma unroll
            for (int pass = 0; pass < 2; pass++) {
                const int coloff = half * 64 + pass * 32;
                uint32_t gr[32], ur[32];
                TC_LD_X32(gr, tmem + blk * 256 + coloff);         // gate
                TC_LD_X32(ur, tmem + blk * 256 + 128 + coloff);   // up
                TC_WAIT_LD();
                if (dstb) {
#pragma unroll
                    for (int c = 0; c < 32; c += 4) {
                        float4 ov;
#pragma unroll
                        for (int q = 0; q < 4; q++) {
                            float gg = __uint_as_float(gr[c + q]) * SCALE;
                            float uu = __uint_as_float(ur[c + q]) * SCALE;
                            (&ov.x)[q] = rtf(gg / (1.f + __expf(-gg)) * uu);
                        }
                        *reinterpret_cast<float4*>(dstb + coloff + c) = ov;
                    }
                }
            }
        }
    }
    __syncthreads();
    if (warp == 0) TC_DEALLOC(tmem, 512);
}

__global__ void __launch_bounds__(NTH, 1)
gemm2_tma_kernel(const __grid_constant__ CUtensorMap mapA,
                 const __grid_constant__ CUtensorMap mapB,
                 float* __restrict__ out) {
    const int e  = blockIdx.z >> 1;
    const int ks = blockIdx.z & 1;
    const int ne = g_count[e];
    const int row0 = blockIdx.y * 256;
    if (row0 >= ne) return;
    const int col0 = blockIdx.x * 256;
    const int kbase = ks * (INTER / 2);
    const bool use2 = (row0 + 128) < ne;

    extern __shared__ char dynsm[];
    __shared__ uint32_t s_tmem;
    __shared__ __align__(8) uint64_t s_full[2], s_mma[2];

    char* sm_c = (char*)(((uintptr_t)dynsm + 1023) & ~(uintptr_t)1023);
    const uint32_t sm_u = smem_u32(sm_c);

    const int tid = threadIdx.x, warp = tid >> 5, lane = tid & 31;
    if (tid < 2) MBAR_INIT(smem_u32(&s_full[tid]), 1);
    else if (tid < 4) MBAR_INIT(smem_u32(&s_mma[tid - 2]), 1);
    if (warp == 0) { TC_ALLOC(smem_u32(&s_tmem), 512); TC_RELINQ(); }
    __syncthreads();
    const uint32_t tmem = s_tmem;
    // TMEM layout: [0,128]=blk0 cols 0-255, [256,384]=blk1 cols 0-255

    const int aY0 = e * TOKENS + row0;
    const int aY1 = aY0 + 128;
    const int bY0 = e * HIDDEN + col0;
    const int bY1 = e * HIDDEN + col0 + 128;

    if (warp == 0 && elect_one()) {
        uint32_t fullu[2], mmau[2];
#pragma unroll
        for (int i = 0; i < 2; i++) { fullu[i] = smem_u32(&s_full[i]); mmau[i] = smem_u32(&s_mma[i]); }

        auto fill = [&](int st) {
            int sl = st & 1;
            uint32_t base = sm_u + sl * STG_BYTES;
            MBAR_EXPECT_TX(fullu[sl], STG_BYTES);
            tma2d(base,                  &mapA, kbase + st * BK, aY0, fullu[sl]);
            tma2d(base + TILE_BYTES,     &mapA, kbase + st * BK, aY1, fullu[sl]);
            tma2d(base + 2 * TILE_BYTES, &mapB, kbase + st * BK, bY0, fullu[sl]);
            tma2d(base + 3 * TILE_BYTES, &mapB, kbase + st * BK, bY1, fullu[sl]);
        };

        fill(0); fill(1);
        const int NS = (INTER / 2) / BK;  // 64
        for (int s = 0; s < NS; s++) {
            MBAR_WAIT(fullu[s & 1], (s >> 1) & 1);
            uint32_t base = sm_u + (s & 1) * STG_BYTES;
            uint64_t a0 = mkdesc(base);
            uint64_t a1 = mkdesc(base + TILE_BYTES);
            uint64_t b0 = mkdesc(base + 2 * TILE_BYTES);
            uint64_t b1 = mkdesc(base + 3 * TILE_BYTES);
            bool en0 = !(s == 0);
#pragma unroll
            for (int k = 0; k < 4; k++) {
                bool en = en0 || k > 0;
                mma_ss_tf32(tmem,       a0 + 2 * k, b0 + 2 * k, MMA_IDESC, en);
                mma_ss_tf32(tmem + 128, a0 + 2 * k, b1 + 2 * k, MMA_IDESC, en);
                if (use2) {
                    mma_ss_tf32(tmem + 256, a1 + 2 * k, b0 + 2 * k, MMA_IDESC, en);
                    mma_ss_tf32(tmem + 384, a1 + 2 * k, b1 + 2 * k, MMA_IDESC, en);
                }
            }
            TC_COMMIT(mmau[s & 1]);
            if (s + 2 < NS) {
                MBAR_WAIT(mmau[s & 1], (s >> 1) & 1);
                fill(s + 2);
            }
        }
        MBAR_WAIT(mmau[(NS - 1) & 1], ((NS - 1) >> 1) & 1);
    }
    __syncthreads();
    TC_FENCE_AFTER();

    // epilogue: out[token] += (w*SCALE) * D; per row-block, 4x 32-col passes/warp
    {
        const int sub = warp & 3, half = warp >> 2;
        const int nblk = use2 ? 2 : 1;
        for (int blk = 0; blk < nblk; blk++) {
            const int slot = row0 + blk * 128 + sub * 32 + lane;
            int tok = 0; float w = 0.f;
            if (slot < ne) { tok = g_tok[e][slot]; w = g_w[e][slot] * SCALE; }
            float* ob = (slot < ne) ? out + (size_t)tok * HIDDEN + col0 : nullptr;
#pragma unroll
            for (int pass = 0; pass < 4; pass++) {
                const int coloff = half * 128 + pass * 32;
                uint32_t d[32];
                TC_LD_X32(d, tmem + blk * 256 + coloff);
                TC_WAIT_LD();
                if (ob) {
#pragma unroll
                    for (int c = 0; c < 32; c++)
                        atomicAdd(ob + coloff + c, w * __uint_as_float(d[c]));
                }
            }
        }
    }
    __syncthreads();
    if (warp == 0) TC_DEALLOC(tmem, 512);
}

// =================================================================
// cp.async fallback GEMMs — round-9 kernels (known-good path)
// =================================================================
template <int NS, typename BRowOf>
__device__ __forceinline__ void mma_mainloop(
    uint32_t smA_u, uint32_t smB_u,
    const float* aBase, size_t aStride,
    uint32_t tmem, const uint32_t* mb, BRowOf&& bRowOf)
{
    const int tid = threadIdx.x, warp = tid >> 5;

    auto fill = [&](int st) {
        uint32_t dA = smA_u + (st % 3) * TILE_BYTES;
        uint32_t dB = smB_u + (st % 3) * TILE_BYTES;
#pragma unroll
        for (int j = 0; j < 4; j++) {
            int i = tid + NTH * j;
            int row = i >> 3, c = i & 7;
            uint32_t so = swz((uint32_t)(row * 128 + c * 16));
            cp16(dA + so, aBase + (size_t)row * aStride + st * BK + c * 4);
            cp16(dB + so, bRowOf(row) + st * BK + c * 4);
        }
        cp_commit();
    };

    fill(0); fill(1);

    for (int s = 0; s < NS; s++) {
        if (s < NS - 1) cp_wait<1>();
        else            cp_wait<0>();
        FENCE_ASYNC();
        __syncthreads();

        if (warp == 0 && elect_one()) {
            uint64_t ad = mkdesc(smA_u + (s % 3) * TILE_BYTES);
            uint64_t bd = mkdesc(smB_u + (s % 3) * TILE_BYTES);
#pragma unroll
            for (int k = 0; k < 4; k++)
                mma_ss_tf32(tmem, ad + 2 * k, bd + 2 * k, MMA_IDESC, !(s == 0 && k == 0));
            TC_COMMIT(mb[s % 3]);
        }

        if (s + 2 < NS) {
            if (s >= 1) MBAR_WAIT(mb[(s - 1) % 3], (((s - 1) / 3) & 1));
            fill(s + 2);
        }
    }
    MBAR_WAIT(mb[(NS - 1) % 3], (((NS - 1) / 3) & 1));
    TC_FENCE_AFTER();
}

__global__ void __launch_bounds__(NTH, 2)
gemm1_kernel(const float* __restrict__ W13) {
    const int e = blockIdx.z;
    const int ne = g_count[e];
    const int row0 = blockIdx.y * 128;
    if (row0 >= ne) return;
    const int col0 = blockIdx.x * 64;

    extern __shared__ char dynsm[];
    __shared__ uint32_t s_tmem;
    __shared__ __align__(8) uint64_t s_mbar[3];
    __shared__ uint32_t s_mb[3];

    char* smA_c = (char*)(((uintptr_t)dynsm + 1023) & ~(uintptr_t)1023);
    const uint32_t smA_u = smem_u32(smA_c);
    const uint32_t smB_u = smA_u + 3 * TILE_BYTES;

    const int tid = threadIdx.x, warp = tid >> 5, lane = tid & 31;
    if (tid < 3) { MBAR_INIT(smem_u32(&s_mbar[tid]), 1); s_mb[tid] = smem_u32(&s_mbar[tid]); }
    if (warp == 0) { TC_ALLOC(smem_u32(&s_tmem), 128); TC_RELINQ(); }
    __syncthreads();
    const uint32_t tmem = s_tmem;

    const float* aBase = g_xg + ((size_t)e * TOKENS + row0) * HIDDEN;
    const float* wBase = W13 + (size_t)e * (2 * INTER) * HIDDEN;

    auto bRowOf = [&](int row) -> const float* {
        int grow = (row < 64) ? (col0 + row) : (INTER + col0 + row - 64);
        return wBase + (size_t)grow * HIDDEN;
    };

    mma_mainloop<HIDDEN / BK>(smA_u, smB_u, aBase, HIDDEN, tmem, s_mb, bRowOf);

    {
        const int sub = warp & 3, half = warp >> 2;
        uint32_t gr[32], ur[32];
        TC_LD_X32(gr, tmem + 32 * half);
        TC_LD_X32(ur, tmem + 64 + 32 * half);
        TC_WAIT_LD();
        const int slot = row0 + sub * 32 + lane;
        if (slot < ne) {
            float* dst = g_act + ((size_t)e * TOKENS + slot) * INTER + col0 + 32 * half;
#pragma unroll
            for (int c = 0; c < 32; c += 4) {
                float4 ov;
#pragma unroll
                for (int q = 0; q < 4; q++) {
                    float gg = __uint_as_float(gr[c + q]) * SCALE;
                    float uu = __uint_as_float(ur[c + q]) * SCALE;
                    (&ov.x)[q] = rtf(gg / (1.f + __expf(-gg)) * uu);
                }
                *reinterpret_cast<float4*>(dst + c) = ov;
            }
        }
    }
    __syncthreads();
    if (warp == 0) TC_DEALLOC(tmem, 128);
}

__global__ void __launch_bounds__(NTH, 2)
gemm2_kernel(const float* __restrict__ W2, float* __restrict__ out) {
    const int e  = blockIdx.z >> 1;
    const int ks = blockIdx.z & 1;
    const int ne = g_count[e];
    const int row0 = blockIdx.y * 128;
    if (row0 >= ne) return;
    const int col0 = blockIdx.x * 128;
    const int kbase = ks * (INTER / 2);

    extern __shared__ char dynsm[];
    __shared__ uint32_t s_tmem;
    __shared__ __align__(8) uint64_t s_mbar[3];
    __shared__ uint32_t s_mb[3];

    char* smA_c = (char*)(((uintptr_t)dynsm + 1023) & ~(uintptr_t)1023);
    const uint32_t smA_u = smem_u32(smA_c);
    const uint32_t smB_u = smA_u + 3 * TILE_BYTES;

    const int tid = threadIdx.x, warp = tid >> 5, lane = tid & 31;
    if (tid < 3) { MBAR_INIT(smem_u32(&s_mbar[tid]), 1); s_mb[tid] = smem_u32(&s_mbar[tid]); }
    if (warp == 0) { TC_ALLOC(smem_u32(&s_tmem), 128); TC_RELINQ(); }
    __syncthreads();
    const uint32_t tmem = s_tmem;

    const float* aBase = g_act + ((size_t)e * TOKENS + row0) * INTER + kbase;
    const float* bBase = W2 + (size_t)e * HIDDEN * INTER + kbase;

    auto bRowOf = [&](int row) -> const float* {
        return bBase + (size_t)(col0 + row) * INTER;
    };

    mma_mainloop<(INTER / 2) / BK>(smA_u, smB_u, aBase, INTER, tmem, s_mb, bRowOf);

    {
        const int sub = warp & 3, half = warp >> 2;
        uint32_t d0[32], d1[32];
        TC_LD_X32(d0, tmem + 64 * half);
        TC_LD_X32(d1, tmem + 64 * half + 32);
        TC_WAIT_LD();
        const int slot = row0 + sub * 32 + lane;
        if (slot < ne) {
            const int tok = g_tok[e][slot];
            const float w = g_w[e][slot] * SCALE;
            float* o = out + (size_t)tok * HIDDEN + col0 + 64 * half;
#pragma unroll
            for (int c = 0; c < 32; c++) atomicAdd(o + c, w * __uint_as_float(d0[c]));
#pragma unroll
            for (int c = 0; c < 32; c++) atomicAdd(o + 32 + c, w * __uint_as_float(d1[c]));
        }
    }
    __syncthreads();
    if (warp == 0) TC_DEALLOC(tmem, 128);
}

#else
// =================================================================
// Fallback (compute_103 PTX pass only; never executes on sm_103a device)
// =================================================================
__device__ __forceinline__ float trunc_tf32(float f) {
    return __uint_as_float(__float_as_uint(f) & 0xFFFFE000u);
}

__global__ void __launch_bounds__(NTH, 2)
gemm1_kernel(const float* __restrict__ W13) {
    const int e = blockIdx.z;
    const int ne = g_count[e];
    const int row0 = blockIdx.y * 128;
    if (row0 >= ne) return;
    const int col0 = blockIdx.x * 64;
    const float* wBase = W13 + (size_t)e * (2 * INTER) * HIDDEN;

    for (int idx = threadIdx.x; idx < 128 * 64; idx += NTH) {
        int rr = idx >> 6, cc = idx & 63;
        int slot = row0 + rr;
        if (slot >= ne) continue;
        const float* a = g_xg + ((size_t)e * TOKENS + slot) * HIDDEN;
        const float* bg = wBase + (size_t)(col0 + cc) * HIDDEN;
        const float* bu = wBase + (size_t)(INTER + col0 + cc) * HIDDEN;
        float sg = 0.f, su = 0.f;
        for (int k = 0; k < HIDDEN; k++) {
            float av = a[k];
            sg += av * trunc_tf32(bg[k]);
            su += av * trunc_tf32(bu[k]);
        }
        sg *= SCALE; su *= SCALE;
        float act = sg / (1.f + __expf(-sg)) * su;
        g_act[((size_t)e * TOKENS + slot) * INTER + col0 + cc] = rtf(act);
    }
}

__global__ void __launch_bounds__(NTH, 2)
gemm2_kernel(const float* __restrict__ W2, float* __restrict__ out) {
    const int e  = blockIdx.z >> 1;
    const int ks = blockIdx.z & 1;
    const int ne = g_count[e];
    const int row0 = blockIdx.y * 128;
    if (row0 >= ne) return;
    const int col0 = blockIdx.x * 128;
    const int kbase = ks * (INTER / 2);
    const float* bBase = W2 + (size_t)e * HIDDEN * INTER;

    for (int idx = threadIdx.x; idx < 128 * 128; idx += NTH) {
        int rr = idx >> 7, cc = idx & 127;
        int slot = row0 + rr;
        if (slot >= ne) continue;
        const float* a = g_act + ((size_t)e * TOKENS + slot) * INTER + kbase;
        const float* b = bBase + (size_t)(col0 + cc) * INTER + kbase;
        float s = 0.f;
        for (int k = 0; k < INTER / 2; k++) s += a[k] * trunc_tf32(b[k]);
        atomicAdd(&out[(size_t)g_tok[e][slot] * HIDDEN + col0 + cc],
                  g_w[e][slot] * SCALE * s);
    }
}

__global__ void __launch_bounds__(NTH, 1)
gemm1_tma_kernel(const __grid_constant__ CUtensorMap mapA,
                 const __grid_constant__ CUtensorMap mapB) {}
__global__ void __launch_bounds__(NTH, 1)
gemm2_tma_kernel(const __grid_constant__ CUtensorMap mapA,
                 const __grid_constant__ CUtensorMap mapB,
                 float* __restrict__ out) {}
#endif  // USE_TC

// ---------------- host: tensormap construction via dlopen ----------------
typedef CUresult (*EncodeTiledFn)(
    CUtensorMap*, CUtensorMapDataType, cuuint32_t, void*,
    const cuuint64_t*, const cuuint64_t*, const cuuint32_t*, const cuuint32_t*,
    CUtensorMapInterleave, CUtensorMapSwizzle, CUtensorMapL2promotion,
    CUtensorMapFloatOOBfill);

static bool make_map2d(EncodeTiledFn fn, CUtensorMap* m, void* base,
                       uint64_t width, uint64_t height, uint32_t box0, uint32_t box1) {
    cuuint64_t dims[2] = {width, height};
    cuuint64_t strides[1] = {width * sizeof(float)};
    cuuint32_t box[2] = {box0, box1};
    cuuint32_t elemstr[2] = {1, 1};
    CUresult r = fn(m, CU_TENSOR_MAP_DATA_TYPE_FLOAT32, 2, base,
                    dims, strides, box, elemstr,
                    CU_TENSOR_MAP_INTERLEAVE_NONE, CU_TENSOR_MAP_SWIZZLE_128B,
                    CU_TENSOR_MAP_L2_PROMOTION_L2_128B,
                    CU_TENSOR_MAP_FLOAT_OOB_FILL_NONE);
    return r == CUDA_SUCCESS;
}

// ---------------- launch ----------------
extern "C" void kernel_launch(void* const* d_in, const int* in_sizes, int n_in,
                              void* d_out, int out_size) {
    const float* X      = (const float*)d_in[0];
    const float* logits = (const float*)d_in[1];
    const float* W13    = (const float*)d_in[2];
    const float* W2     = (const float*)d_in[3];
    float* out = (float*)d_out;

    cudaFuncSetAttribute(gemm1_kernel, cudaFuncAttributeMaxDynamicSharedMemorySize, FB_SMEM);
    cudaFuncSetAttribute(gemm2_kernel, cudaFuncAttributeMaxDynamicSharedMemorySize, FB_SMEM);
    cudaFuncSetAttribute(gemm1_tma_kernel, cudaFuncAttributeMaxDynamicSharedMemorySize, DYN_SMEM);
    cudaFuncSetAttribute(gemm2_tma_kernel, cudaFuncAttributeMaxDynamicSharedMemorySize, DYN_SMEM);

    bool tma_ok = false;
    CUtensorMap mA1, mB1, mA2, mB2;
    {
        void* h = dlopen("libcuda.so.1", RTLD_NOW | RTLD_GLOBAL);
        if (!h) h = dlopen("libcuda.so", RTLD_NOW | RTLD_GLOBAL);
        EncodeTiledFn fn = h ? (EncodeTiledFn)dlsym(h, "cuTensorMapEncodeTiled") : nullptr;
        void *p_xg = nullptr, *p_act = nullptr;
        if (fn &&
            cudaGetSymbolAddress(&p_xg, g_xg) == cudaSuccess &&
            cudaGetSymbolAddress(&p_act, g_act) == cudaSuccess) {
            tma_ok =
                make_map2d(fn, &mA1, p_xg,        HIDDEN, (uint64_t)NEXP * TOKENS,     32, 128) &&
                make_map2d(fn, &mB1, (void*)W13,  HIDDEN, (uint64_t)NEXP * 2 * INTER,  32, 128) &&
                make_map2d(fn, &mA2, p_act,       INTER,  (uint64_t)NEXP * TOKENS,     32, 128) &&
                make_map2d(fn, &mB2, (void*)W2,   INTER,  (uint64_t)NEXP * HIDDEN,     32, 128);
        }
    }

    zero_kernel<<<(TOKENS * HIDDEN / 4) / 256, 256>>>(out);
    router_kernel<<<(TOKENS + 255) / 256, 256>>>(logits);

    dim3 gg(TOKENS, NEXP);
    gather_kernel<<<gg, 256>>>(X);

    if (tma_ok) {
        dim3 g1(INTER / 128, TOKENS / 256, NEXP);          // BM=256, BN=256(g+u)
        dim3 g2(HIDDEN / 256, TOKENS / 256, NEXP * 2);     // BM=256, BN=256, splitK=2
        gemm1_tma_kernel<<<g1, NTH, DYN_SMEM>>>(mA1, mB1);
        gemm2_tma_kernel<<<g2, NTH, DYN_SMEM>>>(mA2, mB2, out);
    } else {
        dim3 g1(INTER / 64, TOKENS / 128, NEXP);
        dim3 g2(HIDDEN / 128, TOKENS / 128, NEXP * 2);
        gemm1_kernel<<<g1, NTH, FB_SMEM>>>(W13);
        gemm2_kernel<<<g2, NTH, FB_SMEM>>>(W2, out);
    }
}

// round 14
// speedup vs baseline: 1.0583x; 1.0583x over previous
#include <cuda_runtime.h>
#include <cuda.h>
#include <dlfcn.h>
#include <cstdint>
#include <cstddef>
#include <cstring>

#define TOKENS 1024
#define HIDDEN 2048
#define INTER  4096
#define NEXP   8
#define NTH    256
#define BK     32
#define TILE_BYTES 16384
#define STG_BYTES  49152                  // A + B0 + B1 per stage
#define DYN_SMEM   (2 * STG_BYTES + 1024) // 2 stages -> 2 CTAs/SM
// Compensation for HW fp32->tf32 truncation of B (mean bias ~2^-11 toward zero)
#define SCALE 1.00048828125f

#if defined(__CUDA_ARCH__) && defined(__CUDA_ARCH_FEAT_SM103_ALL)
#define USE_TC 1
#else
#define USE_TC 0
#endif

// ---------------- device scratch ----------------
__device__ int   g_count[NEXP];
__device__ int   g_tok[NEXP][TOKENS];
__device__ float g_w[NEXP][TOKENS];
__device__ float g_xg[(size_t)NEXP * TOKENS * HIDDEN];   // gathered + tf32-rounded X
__device__ float g_act[(size_t)NEXP * TOKENS * INTER];   // tf32-rounded activations

// ---------------- common helpers ----------------
__device__ __forceinline__ uint32_t f2tf32(float f) {
    uint32_t u;
    asm("cvt.rna.tf32.f32 %0, %1;" : "=r"(u) : "f"(f));
    return u;
}
__device__ __forceinline__ float rtf(float f) { return __uint_as_float(f2tf32(f)); }
__device__ __forceinline__ uint32_t smem_u32(const void* p) {
    uint32_t a;
    asm("{ .reg .u64 t; cvta.to.shared.u64 t, %1; cvt.u32.u64 %0, t; }" : "=r"(a) : "l"(p));
    return a;
}
__device__ __forceinline__ void cp16(uint32_t dst, const float* src) {
    asm volatile("cp.async.cg.shared.global [%0], [%1], 16;\n" :: "r"(dst), "l"(src));
}
__device__ __forceinline__ void cp_commit() { asm volatile("cp.async.commit_group;\n"); }
template <int N> __device__ __forceinline__ void cp_wait() {
    asm volatile("cp.async.wait_group %0;\n" :: "n"(N) : "memory");
}

// ---------------- kernel 0: zero out + counts ----------------
__global__ void zero_kernel(float* __restrict__ out) {
    int i = blockIdx.x * blockDim.x + threadIdx.x;
    reinterpret_cast<float4*>(out)[i] = make_float4(0.f, 0.f, 0.f, 0.f);
    if (blockIdx.x == 0 && threadIdx.x < NEXP) g_count[threadIdx.x] = 0;
}

// ---------------- kernel 1: router ----------------
__global__ void router_kernel(const float* __restrict__ logits) {
    int t = blockIdx.x * blockDim.x + threadIdx.x;
    if (t >= TOKENS) return;
    float l[NEXP];
#pragma unroll
    for (int j = 0; j < NEXP; j++) l[j] = logits[t * NEXP + j];
    int i0 = 0;
#pragma unroll
    for (int j = 1; j < NEXP; j++) if (l[j] > l[i0]) i0 = j;
    int i1 = -1;
#pragma unroll
    for (int j = 0; j < NEXP; j++) {
        if (j == i0) continue;
        if (i1 < 0 || l[j] > l[i1]) i1 = j;
    }
    float e1 = __expf(l[i1] - l[i0]);
    float w1 = e1 / (1.f + e1);
    float w0 = 1.f / (1.f + e1);
    int p0 = atomicAdd(&g_count[i0], 1);
    g_tok[i0][p0] = t;  g_w[i0][p0] = w0;
    int p1 = atomicAdd(&g_count[i1], 1);
    g_tok[i1][p1] = t;  g_w[i1][p1] = w1;
}

// ---------------- kernel 2: gather + tf32-round X ----------------
__global__ void gather_kernel(const float* __restrict__ X) {
    int row = blockIdx.x, e = blockIdx.y;
    if (row >= g_count[e]) return;
    int tok = g_tok[e][row];
    const float4* src = reinterpret_cast<const float4*>(X + (size_t)tok * HIDDEN);
    float4* dst = reinterpret_cast<float4*>(g_xg + ((size_t)e * TOKENS + row) * HIDDEN);
#pragma unroll
    for (int j = 0; j < 2; j++) {
        float4 v = src[threadIdx.x + 256 * j];
        v.x = rtf(v.x); v.y = rtf(v.y); v.z = rtf(v.z); v.w = rtf(v.w);
        dst[threadIdx.x + 256 * j] = v;
    }
}

#if USE_TC
// =================================================================
// tcgen05 helpers
// =================================================================
#define MMA_IDESC ((1u<<4)|(2u<<7)|(2u<<10)|((128u/8)<<17)|((128u/16)<<24))

__device__ __forceinline__ uint32_t elect_one() {
    uint32_t p;
    asm volatile("{\n\t.reg .pred p;\n\telect.sync _|p, 0xFFFFFFFF;\n\tselp.b32 %0, 1, 0, p;\n\t}" : "=r"(p));
    return p;
}
__device__ __forceinline__ uint32_t swz(uint32_t o) { return o ^ ((o >> 3) & 0x70); }
__device__ __forceinline__ uint32_t cl_rank() {
    uint32_t r;
    asm("mov.u32 %0, %%cluster_ctarank;" : "=r"(r));
    return r;
}
#define CLUSTER_SYNC() do {                                                    \
    asm volatile("barrier.cluster.arrive.aligned;" ::: "memory");              \
    asm volatile("barrier.cluster.wait.aligned;" ::: "memory");                \
} while (0)
// Arrive on the mbarrier at the same smem offset in cluster CTA rank 0.
#define MBAR_ARRIVE_R0(addr) do {                                              \
    uint32_t _z = 0;                                                           \
    asm volatile(                                                              \
        "{\n\t.reg .b32 ra;\n\t"                                              \
        "mapa.shared::cluster.u32 ra, %0, %1;\n\t"                            \
        "mbarrier.arrive.shared::cluster.b64 _, [ra];\n\t}"                   \
        :: "r"(addr), "r"(_z) : "memory");                                     \
} while (0)

static constexpr uint64_t DESC_SW128 =
    (2ull << 61) | (1ull << 46) | (64ull << 32) | (1ull << 16);
__device__ __forceinline__ uint64_t mkdesc(uint32_t addr) {
    return DESC_SW128 | ((uint64_t)(addr >> 4) & 0x3FFF);
}
__device__ __forceinline__ void mma_ss_tf32(uint32_t d, uint64_t ad, uint64_t bd,
                                            uint32_t idesc, bool en) {
    uint32_t e = en ? 1u : 0u;
    asm volatile(
        "{\n\t.reg .pred p;\n\tsetp.ne.u32 p, %4, 0;\n\t"
        "tcgen05.mma.cta_group::1.kind::tf32 [%0], %1, %2, %3, p;\n\t}"
        :: "r"(d), "l"(ad), "l"(bd), "r"(idesc), "r"(e) : "memory");
}
#define MBAR_INIT(a, c)  asm volatile("mbarrier.init.shared.b64 [%0], %1;" :: "r"(a), "r"(c) : "memory")
#define MBAR_EXPECT_TX(a, n) asm volatile("mbarrier.arrive.expect_tx.shared.b64 _, [%0], %1;" :: "r"(a), "r"(n) : "memory")
#define TC_COMMIT(a)     asm volatile("tcgen05.commit.cta_group::1.mbarrier::arrive::one.shared::cluster.b64 [%0];" :: "r"(a) : "memory")
#define TC_ALLOC(a, n)   asm volatile("tcgen05.alloc.cta_group::1.sync.aligned.shared::cta.b32 [%0], %1;" :: "r"(a), "r"(n) : "memory")
#define TC_RELINQ()      asm volatile("tcgen05.relinquish_alloc_permit.cta_group::1.sync.aligned;")
#define TC_DEALLOC(t, n) asm volatile("tcgen05.dealloc.cta_group::1.sync.aligned.b32 %0, %1;" :: "r"(t), "r"(n))
#define TC_WAIT_LD()     asm volatile("tcgen05.wait::ld.sync.aligned;" ::: "memory")
#define TC_FENCE_AFTER() asm volatile("tcgen05.fence::after_thread_sync;" ::: "memory")
#define FENCE_ASYNC()    asm volatile("fence.proxy.async.shared::cta;" ::: "memory")
#define MBAR_WAIT(mbar, par) do {                                              \
    uint32_t _m = (mbar), _p = (par);                                          \
    asm volatile(                                                              \
        "{\n\t.reg .pred P1;\n\t"                                             \
        "WL_%=:\n\t"                                                          \
        "mbarrier.try_wait.parity.acquire.cta.shared::cta.b64 P1, [%0], %1, 0x989680;\n\t" \
        "@P1 bra.uni WD_%=;\n\t"                                              \
        "bra.uni WL_%=;\n\t"                                                  \
        "WD_%=:\n\t}"                                                         \
        :: "r"(_m), "r"(_p) : "memory");                                       \
} while (0)
#define TC_LD_X32(r, a)                                                        \
    asm volatile("tcgen05.ld.sync.aligned.32x32b.x32.b32 "                     \
        "{%0,%1,%2,%3,%4,%5,%6,%7,%8,%9,%10,%11,%12,%13,%14,%15,"              \
        "%16,%17,%18,%19,%20,%21,%22,%23,%24,%25,%26,%27,%28,%29,%30,%31}, [%32];" \
        : "=r"((r)[0]),"=r"((r)[1]),"=r"((r)[2]),"=r"((r)[3]),                  \
          "=r"((r)[4]),"=r"((r)[5]),"=r"((r)[6]),"=r"((r)[7]),                  \
          "=r"((r)[8]),"=r"((r)[9]),"=r"((r)[10]),"=r"((r)[11]),                \
          "=r"((r)[12]),"=r"((r)[13]),"=r"((r)[14]),"=r"((r)[15]),              \
          "=r"((r)[16]),"=r"((r)[17]),"=r"((r)[18]),"=r"((r)[19]),              \
          "=r"((r)[20]),"=r"((r)[21]),"=r"((r)[22]),"=r"((r)[23]),              \
          "=r"((r)[24]),"=r"((r)[25]),"=r"((r)[26]),"=r"((r)[27]),              \
          "=r"((r)[28]),"=r"((r)[29]),"=r"((r)[30]),"=r"((r)[31])               \
        : "r"(a))

__device__ __forceinline__ void tma2d(uint32_t smem, const void* tmap,
                                      int x, int y, uint32_t mbar) {
    asm volatile(
        "cp.async.bulk.tensor.2d.shared::cta.global.tile.mbarrier::complete_tx::bytes "
        "[%0], [%1, {%2, %3}], [%4];"
        :: "r"(smem), "l"(tmap), "r"(x), "r"(y), "r"(mbar) : "memory");
}
__device__ __forceinline__ void tma2d_mc(uint32_t smem, const void* tmap,
                                         int x, int y, uint32_t mbar, uint16_t mask) {
    asm volatile(
        "cp.async.bulk.tensor.2d.shared::cluster.global.tile.mbarrier::complete_tx::bytes.multicast::cluster "
        "[%0], [%1, {%2, %3}], [%4], %5;"
        :: "r"(smem), "l"(tmap), "r"(x), "r"(y), "r"(mbar), "h"(mask) : "memory");
}

// =================================================================
// TMA GEMMs, BM=128 x BN=256, cluster (1,2,1): paired row-block CTAs
// share B via TMA multicast (rank0 issues). Each CTA: full[2] (expect
// 48KB = own A + mc B), mma[2]; rank0: bfree[2] signalled by rank1's
// remote arrive when its B slot is reusable. 2 stages, 2 CTAs/SM.
// =================================================================
__global__ void __launch_bounds__(NTH, 2) __cluster_dims__(1, 2, 1)
gemm1_tma_kernel(const __grid_constant__ CUtensorMap mapA,
                 const __grid_constant__ CUtensorMap mapB) {
    const int e = blockIdx.z;
    const int ne = g_count[e];
    const int row0 = blockIdx.y * 128;
    if ((int)((blockIdx.y & ~1u) * 128) >= ne) return;   // whole pair inactive
    const bool active = row0 < ne;
    const int col0 = blockIdx.x * 128;   // 128 gate + 128 up cols
    const uint32_t rank = cl_rank();     // 0 or 1 within pair

    extern __shared__ char dynsm[];
    __shared__ uint32_t s_tmem;
    __shared__ __align__(8) uint64_t s_full[2], s_mma[2], s_bfree[2];

    char* sm_c = (char*)(((uintptr_t)dynsm + 1023) & ~(uintptr_t)1023);
    const uint32_t sm_u = smem_u32(sm_c);

    const int tid = threadIdx.x, warp = tid >> 5, lane = tid & 31;
    if (tid < 2) MBAR_INIT(smem_u32(&s_full[tid]), 1);
    else if (tid < 4) MBAR_INIT(smem_u32(&s_mma[tid - 2]), 1);
    else if (tid < 6) MBAR_INIT(smem_u32(&s_bfree[tid - 4]), 1);
    if (warp == 0) { TC_ALLOC(smem_u32(&s_tmem), 256); TC_RELINQ(); }
    __syncthreads();
    CLUSTER_SYNC();     // barriers visible cluster-wide before any multicast
    const uint32_t tmem = s_tmem;

    const int aY  = e * TOKENS + row0;
    const int bYg = e * (2 * INTER) + col0;
    const int bYu = e * (2 * INTER) + INTER + col0;

    if (warp == 0 && elect_one()) {
        uint32_t fullu[2], mmau[2], bfu[2];
#pragma unroll
        for (int i = 0; i < 2; i++) {
            fullu[i] = smem_u32(&s_full[i]);
            mmau[i]  = smem_u32(&s_mma[i]);
            bfu[i]   = smem_u32(&s_bfree[i]);
        }

        auto fill = [&](int st) {
            int sl = st & 1;
            uint32_t base = sm_u + sl * STG_BYTES;
            MBAR_EXPECT_TX(fullu[sl], STG_BYTES);
            tma2d(base, &mapA, st * BK, aY, fullu[sl]);
            if (rank == 0) {
                MBAR_WAIT(bfu[sl], (st >> 1) & 1);       // partner's B slot free
                tma2d_mc(base + TILE_BYTES,     &mapB, st * BK, bYg, fullu[sl], 0x3);
                tma2d_mc(base + 2 * TILE_BYTES, &mapB, st * BK, bYu, fullu[sl], 0x3);
            } else {
                MBAR_ARRIVE_R0(bfu[sl]);                 // my B slot is free
            }
        };

        fill(0); fill(1);
        const int NS = HIDDEN / BK;  // 64
        for (int s = 0; s < NS; s++) {
            MBAR_WAIT(fullu[s & 1], (s >> 1) & 1);
            if (active) {
                uint32_t base = sm_u + (s & 1) * STG_BYTES;
                uint64_t ad  = mkdesc(base);
                uint64_t bd0 = mkdesc(base + TILE_BYTES);
                uint64_t bd1 = mkdesc(base + 2 * TILE_BYTES);
#pragma unroll
                for (int k = 0; k < 4; k++)
                    mma_ss_tf32(tmem, ad + 2 * k, bd0 + 2 * k, MMA_IDESC, !(s == 0 && k == 0));
#pragma unroll
                for (int k = 0; k < 4; k++)
                    mma_ss_tf32(tmem + 128, ad + 2 * k, bd1 + 2 * k, MMA_IDESC, !(s == 0 && k == 0));
                TC_COMMIT(mmau[s & 1]);
            }
            if (s + 2 < NS) {
                if (active) MBAR_WAIT(mmau[s & 1], (s >> 1) & 1);
                fill(s + 2);
            }
        }
        if (active) MBAR_WAIT(mmau[(NS - 1) & 1], ((NS - 1) >> 1) & 1);
    }
    __syncthreads();
    TC_FENCE_AFTER();

    // epilogue: act = silu(g*SCALE)*(u*SCALE); 2x 32-col passes per warp
    {
        const int sub = warp & 3, half = warp >> 2;
        const int slot = row0 + sub * 32 + lane;
        float* dstb = (slot < ne)
            ? g_act + ((size_t)e * TOKENS + slot) * INTER + col0 : nullptr;
#pragma unroll
        for (int pass = 0; pass < 2; pass++) {
            const int coloff = half * 64 + pass * 32;
            uint32_t gr[32], ur[32];
            TC_LD_X32(gr, tmem + coloff);         // D0 = gate
            TC_LD_X32(ur, tmem + 128 + coloff);   // D1 = up
            TC_WAIT_LD();
            if (dstb) {
#pragma unroll
                for (int c = 0; c < 32; c += 4) {
                    float4 ov;
#pragma unroll
                    for (int q = 0; q < 4; q++) {
                        float gg = __uint_as_float(gr[c + q]) * SCALE;
                        float uu = __uint_as_float(ur[c + q]) * SCALE;
                        (&ov.x)[q] = rtf(gg / (1.f + __expf(-gg)) * uu);
                    }
                    *reinterpret_cast<float4*>(dstb + coloff + c) = ov;
                }
            }
        }
    }
    __syncthreads();
    if (warp == 0) TC_DEALLOC(tmem, 256);
    CLUSTER_SYNC();     // no CTA exits while peer multicast may target it
}

__global__ void __launch_bounds__(NTH, 2) __cluster_dims__(1, 2, 1)
gemm2_tma_kernel(const __grid_constant__ CUtensorMap mapA,
                 const __grid_constant__ CUtensorMap mapB,
                 float* __restrict__ out) {
    const int e  = blockIdx.z >> 1;
    const int ks = blockIdx.z & 1;
    const int ne = g_count[e];
    const int row0 = blockIdx.y * 128;
    if ((int)((blockIdx.y & ~1u) * 128) >= ne) return;
    const bool active = row0 < ne;
    const int col0 = blockIdx.x * 256;
    const int kbase = ks * (INTER / 2);
    const uint32_t rank = cl_rank();

    extern __shared__ char dynsm[];
    __shared__ uint32_t s_tmem;
    __shared__ __align__(8) uint64_t s_full[2], s_mma[2], s_bfree[2];

    char* sm_c = (char*)(((uintptr_t)dynsm + 1023) & ~(uintptr_t)1023);
    const uint32_t sm_u = smem_u32(sm_c);

    const int tid = threadIdx.x, warp = tid >> 5, lane = tid & 31;
    if (tid < 2) MBAR_INIT(smem_u32(&s_full[tid]), 1);
    else if (tid < 4) MBAR_INIT(smem_u32(&s_mma[tid - 2]), 1);
    else if (tid < 6) MBAR_INIT(smem_u32(&s_bfree[tid - 4]), 1);
    if (warp == 0) { TC_ALLOC(smem_u32(&s_tmem), 256); TC_RELINQ(); }
    __syncthreads();
    CLUSTER_SYNC();
    const uint32_t tmem = s_tmem;

    const int aY = e * TOKENS + row0;
    const int bY0 = e * HIDDEN + col0;
    const int bY1 = e * HIDDEN + col0 + 128;

    if (warp == 0 && elect_one()) {
        uint32_t fullu[2], mmau[2], bfu[2];
#pragma unroll
        for (int i = 0; i < 2; i++) {
            fullu[i] = smem_u32(&s_full[i]);
            mmau[i]  = smem_u32(&s_mma[i]);
            bfu[i]   = smem_u32(&s_bfree[i]);
        }

        auto fill = [&](int st) {
            int sl = st & 1;
            uint32_t base = sm_u + sl * STG_BYTES;
            MBAR_EXPECT_TX(fullu[sl], STG_BYTES);
            tma2d(base, &mapA, kbase + st * BK, aY, fullu[sl]);
            if (rank == 0) {
                MBAR_WAIT(bfu[sl], (st >> 1) & 1);
                tma2d_mc(base + TILE_BYTES,     &mapB, kbase + st * BK, bY0, fullu[sl], 0x3);
                tma2d_mc(base + 2 * TILE_BYTES, &mapB, kbase + st * BK, bY1, fullu[sl], 0x3);
            } else {
                MBAR_ARRIVE_R0(bfu[sl]);
            }
        };

        fill(0); fill(1);
        const int NS = (INTER / 2) / BK;  // 64
        for (int s = 0; s < NS; s++) {
            MBAR_WAIT(fullu[s & 1], (s >> 1) & 1);
            if (active) {
                uint32_t base = sm_u + (s & 1) * STG_BYTES;
                uint64_t ad  = mkdesc(base);
                uint64_t bd0 = mkdesc(base + TILE_BYTES);
                uint64_t bd1 = mkdesc(base + 2 * TILE_BYTES);
#pragma unroll
                for (int k = 0; k < 4; k++)
                    mma_ss_tf32(tmem, ad + 2 * k, bd0 + 2 * k, MMA_IDESC, !(s == 0 && k == 0));
#pragma unroll
                for (int k = 0; k < 4; k++)
                    mma_ss_tf32(tmem + 128, ad + 2 * k, bd1 + 2 * k, MMA_IDESC, !(s == 0 && k == 0));
                TC_COMMIT(mmau[s & 1]);
            }
            if (s + 2 < NS) {
                if (active) MBAR_WAIT(mmau[s & 1], (s >> 1) & 1);
                fill(s + 2);
            }
        }
        if (active) MBAR_WAIT(mmau[(NS - 1) & 1], ((NS - 1) >> 1) & 1);
    }
    __syncthreads();
    TC_FENCE_AFTER();

    // epilogue: out[token] += (w*SCALE) * D over 256 cols; 2 blocks x 64/warp
    {
        const int sub = warp & 3, half = warp >> 2;
        const int slot = row0 + sub * 32 + lane;
        int tok = 0; float w = 0.f;
        if (slot < ne) { tok = g_tok[e][slot]; w = g_w[e][slot] * SCALE; }
#pragma unroll
        for (int blk = 0; blk < 2; blk++) {
            uint32_t d0[32], d1[32];
            TC_LD_X32(d0, tmem + blk * 128 + half * 64);
            TC_LD_X32(d1, tmem + blk * 128 + half * 64 + 32);
            TC_WAIT_LD();
            if (slot < ne) {
                float* o = out + (size_t)tok * HIDDEN + col0 + blk * 128 + half * 64;
#pragma unroll
                for (int c = 0; c < 32; c++) atomicAdd(o + c, w * __uint_as_float(d0[c]));
#pragma unroll
                for (int c = 0; c < 32; c++) atomicAdd(o + 32 + c, w * __uint_as_float(d1[c]));
            }
        }
    }
    __syncthreads();
    if (warp == 0) TC_DEALLOC(tmem, 256);
    CLUSTER_SYNC();
}

// =================================================================
// cp.async fallback GEMMs — round-9 kernels (known-good path)
// =================================================================
template <int NS, typename BRowOf>
__device__ __forceinline__ void mma_mainloop(
    uint32_t smA_u, uint32_t smB_u,
    const float* aBase, size_t aStride,
    uint32_t tmem, const uint32_t* mb, BRowOf&& bRowOf)
{
    const int tid = threadIdx.x, warp = tid >> 5;

    auto fill = [&](int st) {
        uint32_t dA = smA_u + (st % 3) * TILE_BYTES;
        uint32_t dB = smB_u + (st % 3) * TILE_BYTES;
#pragma unroll
        for (int j = 0; j < 4; j++) {
            int i = tid + NTH * j;
            int row = i >> 3, c = i & 7;
            uint32_t so = swz((uint32_t)(row * 128 + c * 16));
            cp16(dA + so, aBase + (size_t)row * aStride + st * BK + c * 4);
            cp16(dB + so, bRowOf(row) + st * BK + c * 4);
        }
        cp_commit();
    };

    fill(0); fill(1);

    for (int s = 0; s < NS; s++) {
        if (s < NS - 1) cp_wait<1>();
        else            cp_wait<0>();
        FENCE_ASYNC();
        __syncthreads();

        if (warp == 0 && elect_one()) {
            uint64_t ad = mkdesc(smA_u + (s % 3) * TILE_BYTES);
            uint64_t bd = mkdesc(smB_u + (s % 3) * TILE_BYTES);
#pragma unroll
            for (int k = 0; k < 4; k++)
                mma_ss_tf32(tmem, ad + 2 * k, bd + 2 * k, MMA_IDESC, !(s == 0 && k == 0));
            TC_COMMIT(mb[s % 3]);
        }

        if (s + 2 < NS) {
            if (s >= 1) MBAR_WAIT(mb[(s - 1) % 3], (((s - 1) / 3) & 1));
            fill(s + 2);
        }
    }
    MBAR_WAIT(mb[(NS - 1) % 3], (((NS - 1) / 3) & 1));
    TC_FENCE_AFTER();
}

__global__ void __launch_bounds__(NTH, 2)
gemm1_kernel(const float* __restrict__ W13) {
    const int e = blockIdx.z;
    const int ne = g_count[e];
    const int row0 = blockIdx.y * 128;
    if (row0 >= ne) return;
    const int col0 = blockIdx.x * 64;

    extern __shared__ char dynsm[];
    __shared__ uint32_t s_tmem;
    __shared__ __align__(8) uint64_t s_mbar[3];
    __shared__ uint32_t s_mb[3];

    char* smA_c = (char*)(((uintptr_t)dynsm + 1023) & ~(uintptr_t)1023);
    const uint32_t smA_u = smem_u32(smA_c);
    const uint32_t smB_u = smA_u + 3 * TILE_BYTES;

    const int tid = threadIdx.x, warp = tid >> 5, lane = tid & 31;
    if (tid < 3) { MBAR_INIT(smem_u32(&s_mbar[tid]), 1); s_mb[tid] = smem_u32(&s_mbar[tid]); }
    if (warp == 0) { TC_ALLOC(smem_u32(&s_tmem), 128); TC_RELINQ(); }
    __syncthreads();
    const uint32_t tmem = s_tmem;

    const float* aBase = g_xg + ((size_t)e * TOKENS + row0) * HIDDEN;
    const float* wBase = W13 + (size_t)e * (2 * INTER) * HIDDEN;

    auto bRowOf = [&](int row) -> const float* {
        int grow = (row < 64) ? (col0 + row) : (INTER + col0 + row - 64);
        return wBase + (size_t)grow * HIDDEN;
    };

    mma_mainloop<HIDDEN / BK>(smA_u, smB_u, aBase, HIDDEN, tmem, s_mb, bRowOf);

    {
        const int sub = warp & 3, half = warp >> 2;
        uint32_t gr[32], ur[32];
        TC_LD_X32(gr, tmem + 32 * half);
        TC_LD_X32(ur, tmem + 64 + 32 * half);
        TC_WAIT_LD();
        const int slot = row0 + sub * 32 + lane;
        if (slot < ne) {
            float* dst = g_act + ((size_t)e * TOKENS + slot) * INTER + col0 + 32 * half;
#pragma unroll
            for (int c = 0; c < 32; c += 4) {
                float4 ov;
#pragma unroll
                for (int q = 0; q < 4; q++) {
                    float gg = __uint_as_float(gr[c + q]) * SCALE;
                    float uu = __uint_as_float(ur[c + q]) * SCALE;
                    (&ov.x)[q] = rtf(gg / (1.f + __expf(-gg)) * uu);
                }
                *reinterpret_cast<float4*>(dst + c) = ov;
            }
        }
    }
    __syncthreads();
    if (warp == 0) TC_DEALLOC(tmem, 128);
}

__global__ void __launch_bounds__(NTH, 2)
gemm2_kernel(const float* __restrict__ W2, float* __restrict__ out) {
    const int e  = blockIdx.z >> 1;
    const int ks = blockIdx.z & 1;
    const int ne = g_count[e];
    const int row0 = blockIdx.y * 128;
    if (row0 >= ne) return;
    const int col0 = blockIdx.x * 128;
    const int kbase = ks * (INTER / 2);

    extern __shared__ char dynsm[];
    __shared__ uint32_t s_tmem;
    __shared__ __align__(8) uint64_t s_mbar[3];
    __shared__ uint32_t s_mb[3];

    char* smA_c = (char*)(((uintptr_t)dynsm + 1023) & ~(uintptr_t)1023);
    const uint32_t smA_u = smem_u32(smA_c);
    const uint32_t smB_u = smA_u + 3 * TILE_BYTES;

    const int tid = threadIdx.x, warp = tid >> 5, lane = tid & 31;
    if (tid < 3) { MBAR_INIT(smem_u32(&s_mbar[tid]), 1); s_mb[tid] = smem_u32(&s_mbar[tid]); }
    if (warp == 0) { TC_ALLOC(smem_u32(&s_tmem), 128); TC_RELINQ(); }
    __syncthreads();
    const uint32_t tmem = s_tmem;

    const float* aBase = g_act + ((size_t)e * TOKENS + row0) * INTER + kbase;
    const float* bBase = W2 + (size_t)e * HIDDEN * INTER + kbase;

    auto bRowOf = [&](int row) -> const float* {
        return bBase + (size_t)(col0 + row) * INTER;
    };

    mma_mainloop<(INTER / 2) / BK>(smA_u, smB_u, aBase, INTER, tmem, s_mb, bRowOf);

    {
        const int sub = warp & 3, half = warp >> 2;
        uint32_t d0[32], d1[32];
        TC_LD_X32(d0, tmem + 64 * half);
        TC_LD_X32(d1, tmem + 64 * half + 32);
        TC_WAIT_LD();
        const int slot = row0 + sub * 32 + lane;
        if (slot < ne) {
            const int tok = g_tok[e][slot];
            const float w = g_w[e][slot] * SCALE;
            float* o = out + (size_t)tok * HIDDEN + col0 + 64 * half;
#pragma unroll
            for (int c = 0; c < 32; c++) atomicAdd(o + c, w * __uint_as_float(d0[c]));
#pragma unroll
            for (int c = 0; c < 32; c++) atomicAdd(o + 32 + c, w * __uint_as_float(d1[c]));
        }
    }
    __syncthreads();
    if (warp == 0) TC_DEALLOC(tmem, 128);
}

#else
// =================================================================
// Fallback (compute_103 PTX pass only; never executes on sm_103a device)
// =================================================================
__device__ __forceinline__ float trunc_tf32(float f) {
    return __uint_as_float(__float_as_uint(f) & 0xFFFFE000u);
}

__global__ void __launch_bounds__(NTH, 2)
gemm1_kernel(const float* __restrict__ W13) {
    const int e = blockIdx.z;
    const int ne = g_count[e];
    const int row0 = blockIdx.y * 128;
    if (row0 >= ne) return;
    const int col0 = blockIdx.x * 64;
    const float* wBase = W13 + (size_t)e * (2 * INTER) * HIDDEN;

    for (int idx = threadIdx.x; idx < 128 * 64; idx += NTH) {
        int rr = idx >> 6, cc = idx & 63;
        int slot = row0 + rr;
        if (slot >= ne) continue;
        const float* a = g_xg + ((size_t)e * TOKENS + slot) * HIDDEN;
        const float* bg = wBase + (size_t)(col0 + cc) * HIDDEN;
        const float* bu = wBase + (size_t)(INTER + col0 + cc) * HIDDEN;
        float sg = 0.f, su = 0.f;
        for (int k = 0; k < HIDDEN; k++) {
            float av = a[k];
            sg += av * trunc_tf32(bg[k]);
            su += av * trunc_tf32(bu[k]);
        }
        sg *= SCALE; su *= SCALE;
        float act = sg / (1.f + __expf(-sg)) * su;
        g_act[((size_t)e * TOKENS + slot) * INTER + col0 + cc] = rtf(act);
    }
}

__global__ void __launch_bounds__(NTH, 2)
gemm2_kernel(const float* __restrict__ W2, float* __restrict__ out) {
    const int e  = blockIdx.z >> 1;
    const int ks = blockIdx.z & 1;
    const int ne = g_count[e];
    const int row0 = blockIdx.y * 128;
    if (row0 >= ne) return;
    const int col0 = blockIdx.x * 128;
    const int kbase = ks * (INTER / 2);
    const float* bBase = W2 + (size_t)e * HIDDEN * INTER;

    for (int idx = threadIdx.x; idx < 128 * 128; idx += NTH) {
        int rr = idx >> 7, cc = idx & 127;
        int slot = row0 + rr;
        if (slot >= ne) continue;
        const float* a = g_act + ((size_t)e * TOKENS + slot) * INTER + kbase;
        const float* b = bBase + (size_t)(col0 + cc) * INTER + kbase;
        float s = 0.f;
        for (int k = 0; k < INTER / 2; k++) s += a[k] * trunc_tf32(b[k]);
        atomicAdd(&out[(size_t)g_tok[e][slot] * HIDDEN + col0 + cc],
                  g_w[e][slot] * SCALE * s);
    }
}

__global__ void __launch_bounds__(NTH, 2) __cluster_dims__(1, 2, 1)
gemm1_tma_kernel(const __grid_constant__ CUtensorMap mapA,
                 const __grid_constant__ CUtensorMap mapB) {}
__global__ void __launch_bounds__(NTH, 2) __cluster_dims__(1, 2, 1)
gemm2_tma_kernel(const __grid_constant__ CUtensorMap mapA,
                 const __grid_constant__ CUtensorMap mapB,
                 float* __restrict__ out) {}
#endif  // USE_TC

// ---------------- host: tensormap construction via dlopen ----------------
typedef CUresult (*EncodeTiledFn)(
    CUtensorMap*, CUtensorMapDataType, cuuint32_t, void*,
    const cuuint64_t*, const cuuint64_t*, const cuuint32_t*, const cuuint32_t*,
    CUtensorMapInterleave, CUtensorMapSwizzle, CUtensorMapL2promotion,
    CUtensorMapFloatOOBfill);

static bool make_map2d(EncodeTiledFn fn, CUtensorMap* m, void* base,
                       uint64_t width, uint64_t height, uint32_t box0, uint32_t box1) {
    cuuint64_t dims[2] = {width, height};
    cuuint64_t strides[1] = {width * sizeof(float)};
    cuuint32_t box[2] = {box0, box1};
    cuuint32_t elemstr[2] = {1, 1};
    CUresult r = fn(m, CU_TENSOR_MAP_DATA_TYPE_FLOAT32, 2, base,
                    dims, strides, box, elemstr,
                    CU_TENSOR_MAP_INTERLEAVE_NONE, CU_TENSOR_MAP_SWIZZLE_128B,
                    CU_TENSOR_MAP_L2_PROMOTION_L2_128B,
                    CU_TENSOR_MAP_FLOAT_OOB_FILL_NONE);
    return r == CUDA_SUCCESS;
}

// ---------------- launch ----------------
extern "C" void kernel_launch(void* const* d_in, const int* in_sizes, int n_in,
                              void* d_out, int out_size) {
    const float* X      = (const float*)d_in[0];
    const float* logits = (const float*)d_in[1];
    const float* W13    = (const float*)d_in[2];
    const float* W2     = (const float*)d_in[3];
    float* out = (float*)d_out;

    cudaFuncSetAttribute(gemm1_kernel, cudaFuncAttributeMaxDynamicSharedMemorySize, DYN_SMEM);
    cudaFuncSetAttribute(gemm2_kernel, cudaFuncAttributeMaxDynamicSharedMemorySize, DYN_SMEM);
    cudaFuncSetAttribute(gemm1_tma_kernel, cudaFuncAttributeMaxDynamicSharedMemorySize, DYN_SMEM);
    cudaFuncSetAttribute(gemm2_tma_kernel, cudaFuncAttributeMaxDynamicSharedMemorySize, DYN_SMEM);

    bool tma_ok = false;
    CUtensorMap mA1, mB1, mA2, mB2;
    {
        void* h = dlopen("libcuda.so.1", RTLD_NOW | RTLD_GLOBAL);
        if (!h) h = dlopen("libcuda.so", RTLD_NOW | RTLD_GLOBAL);
        EncodeTiledFn fn = h ? (EncodeTiledFn)dlsym(h, "cuTensorMapEncodeTiled") : nullptr;
        void *p_xg = nullptr, *p_act = nullptr;
        if (fn &&
            cudaGetSymbolAddress(&p_xg, g_xg) == cudaSuccess &&
            cudaGetSymbolAddress(&p_act, g_act) == cudaSuccess) {
            tma_ok =
                make_map2d(fn, &mA1, p_xg,        HIDDEN, (uint64_t)NEXP * TOKENS,     32, 128) &&
                make_map2d(fn, &mB1, (void*)W13,  HIDDEN, (uint64_t)NEXP * 2 * INTER,  32, 128) &&
                make_map2d(fn, &mA2, p_act,       INTER,  (uint64_t)NEXP * TOKENS,     32, 128) &&
                make_map2d(fn, &mB2, (void*)W2,   INTER,  (uint64_t)NEXP * HIDDEN,     32, 128);
        }
    }

    zero_kernel<<<(TOKENS * HIDDEN / 4) / 256, 256>>>(out);
    router_kernel<<<(TOKENS + 255) / 256, 256>>>(logits);

    dim3 gg(TOKENS, NEXP);
    gather_kernel<<<gg, 256>>>(X);

    if (tma_ok) {
        dim3 g1(INTER / 128, TOKENS / 128, NEXP);          // y paired via cluster
        dim3 g2(HIDDEN / 256, TOKENS / 128, NEXP * 2);
        gemm1_tma_kernel<<<g1, NTH, DYN_SMEM>>>(mA1, mB1);
        gemm2_tma_kernel<<<g2, NTH, DYN_SMEM>>>(mA2, mB2, out);
    } else {
        dim3 g1(INTER / 64, TOKENS / 128, NEXP);
        dim3 g2(HIDDEN / 128, TOKENS / 128, NEXP * 2);
        gemm1_kernel<<<g1, NTH, DYN_SMEM>>>(W13);
        gemm2_kernel<<<g2, NTH, DYN_SMEM>>>(W2, out);
    }
}

// round 15
// speedup vs baseline: 1.1678x; 1.1035x over previous
#include <cuda_runtime.h>
#include <cuda.h>
#include <dlfcn.h>
#include <cstdint>
#include <cstddef>
#include <cstring>

#define TOKENS 1024
#define HIDDEN 2048
#define INTER  4096
#define NEXP   8
#define NTH    256
#define BK     32
#define TILE_BYTES 16384
#define STG_BYTES  49152                  // A + B0 + B1 per stage
#define DYN_SMEM   (2 * STG_BYTES + 1024) // 2 stages -> 2 CTAs/SM
// Compensation for HW fp32->tf32 truncation of B (mean bias ~2^-11 toward zero)
#define SCALE 1.00048828125f

#if defined(__CUDA_ARCH__) && defined(__CUDA_ARCH_FEAT_SM103_ALL)
#define USE_TC 1
#else
#define USE_TC 0
#endif

// ---------------- device scratch ----------------
__device__ int   g_count[NEXP];
__device__ int   g_tok[NEXP][TOKENS];
__device__ float g_w[NEXP][TOKENS];
__device__ float g_xg[(size_t)NEXP * TOKENS * HIDDEN];   // gathered + tf32-rounded X
__device__ float g_act[(size_t)NEXP * TOKENS * INTER];   // tf32-rounded activations

// ---------------- common helpers ----------------
__device__ __forceinline__ uint32_t f2tf32(float f) {
    uint32_t u;
    asm("cvt.rna.tf32.f32 %0, %1;" : "=r"(u) : "f"(f));
    return u;
}
__device__ __forceinline__ float rtf(float f) { return __uint_as_float(f2tf32(f)); }
__device__ __forceinline__ uint32_t smem_u32(const void* p) {
    uint32_t a;
    asm("{ .reg .u64 t; cvta.to.shared.u64 t, %1; cvt.u32.u64 %0, t; }" : "=r"(a) : "l"(p));
    return a;
}
__device__ __forceinline__ void cp16(uint32_t dst, const float* src) {
    asm volatile("cp.async.cg.shared.global [%0], [%1], 16;\n" :: "r"(dst), "l"(src));
}
__device__ __forceinline__ void cp_commit() { asm volatile("cp.async.commit_group;\n"); }
template <int N> __device__ __forceinline__ void cp_wait() {
    asm volatile("cp.async.wait_group %0;\n" :: "n"(N) : "memory");
}

// ---------------- kernel 0: zero out + counts ----------------
__global__ void zero_kernel(float* __restrict__ out) {
    int i = blockIdx.x * blockDim.x + threadIdx.x;
    reinterpret_cast<float4*>(out)[i] = make_float4(0.f, 0.f, 0.f, 0.f);
    if (blockIdx.x == 0 && threadIdx.x < NEXP) g_count[threadIdx.x] = 0;
}

// ---------------- kernel 1: router ----------------
__global__ void router_kernel(const float* __restrict__ logits) {
    int t = blockIdx.x * blockDim.x + threadIdx.x;
    if (t >= TOKENS) return;
    float l[NEXP];
#pragma unroll
    for (int j = 0; j < NEXP; j++) l[j] = logits[t * NEXP + j];
    int i0 = 0;
#pragma unroll
    for (int j = 1; j < NEXP; j++) if (l[j] > l[i0]) i0 = j;
    int i1 = -1;
#pragma unroll
    for (int j = 0; j < NEXP; j++) {
        if (j == i0) continue;
        if (i1 < 0 || l[j] > l[i1]) i1 = j;
    }
    float e1 = __expf(l[i1] - l[i0]);
    float w1 = e1 / (1.f + e1);
    float w0 = 1.f / (1.f + e1);
    int p0 = atomicAdd(&g_count[i0], 1);
    g_tok[i0][p0] = t;  g_w[i0][p0] = w0;
    int p1 = atomicAdd(&g_count[i1], 1);
    g_tok[i1][p1] = t;  g_w[i1][p1] = w1;
}

// ---------------- kernel 2: gather + tf32-round X ----------------
__global__ void gather_kernel(const float* __restrict__ X) {
    int row = blockIdx.x, e = blockIdx.y;
    if (row >= g_count[e]) return;
    int tok = g_tok[e][row];
    const float4* src = reinterpret_cast<const float4*>(X + (size_t)tok * HIDDEN);
    float4* dst = reinterpret_cast<float4*>(g_xg + ((size_t)e * TOKENS + row) * HIDDEN);
#pragma unroll
    for (int j = 0; j < 2; j++) {
        float4 v = src[threadIdx.x + 256 * j];
        v.x = rtf(v.x); v.y = rtf(v.y); v.z = rtf(v.z); v.w = rtf(v.w);
        dst[threadIdx.x + 256 * j] = v;
    }
}

#if USE_TC
// =================================================================
// tcgen05 helpers
// =================================================================
#define MMA_IDESC ((1u<<4)|(2u<<7)|(2u<<10)|((128u/8)<<17)|((128u/16)<<24))

__device__ __forceinline__ uint32_t elect_one() {
    uint32_t p;
    asm volatile("{\n\t.reg .pred p;\n\telect.sync _|p, 0xFFFFFFFF;\n\tselp.b32 %0, 1, 0, p;\n\t}" : "=r"(p));
    return p;
}
__device__ __forceinline__ uint32_t swz(uint32_t o) { return o ^ ((o >> 3) & 0x70); }

static constexpr uint64_t DESC_SW128 =
    (2ull << 61) | (1ull << 46) | (64ull << 32) | (1ull << 16);
__device__ __forceinline__ uint64_t mkdesc(uint32_t addr) {
    return DESC_SW128 | ((uint64_t)(addr >> 4) & 0x3FFF);
}
__device__ __forceinline__ void mma_ss_tf32(uint32_t d, uint64_t ad, uint64_t bd,
                                            uint32_t idesc, bool en) {
    uint32_t e = en ? 1u : 0u;
    asm volatile(
        "{\n\t.reg .pred p;\n\tsetp.ne.u32 p, %4, 0;\n\t"
        "tcgen05.mma.cta_group::1.kind::tf32 [%0], %1, %2, %3, p;\n\t}"
        :: "r"(d), "l"(ad), "l"(bd), "r"(idesc), "r"(e) : "memory");
}
#define MBAR_INIT(a, c)  asm volatile("mbarrier.init.shared.b64 [%0], %1;" :: "r"(a), "r"(c) : "memory")
#define MBAR_EXPECT_TX(a, n) asm volatile("mbarrier.arrive.expect_tx.shared.b64 _, [%0], %1;" :: "r"(a), "r"(n) : "memory")
#define TC_COMMIT(a)     asm volatile("tcgen05.commit.cta_group::1.mbarrier::arrive::one.shared::cluster.b64 [%0];" :: "r"(a) : "memory")
#define TC_ALLOC(a, n)   asm volatile("tcgen05.alloc.cta_group::1.sync.aligned.shared::cta.b32 [%0], %1;" :: "r"(a), "r"(n) : "memory")
#define TC_RELINQ()      asm volatile("tcgen05.relinquish_alloc_permit.cta_group::1.sync.aligned;")
#define TC_DEALLOC(t, n) asm volatile("tcgen05.dealloc.cta_group::1.sync.aligned.b32 %0, %1;" :: "r"(t), "r"(n))
#define TC_WAIT_LD()     asm volatile("tcgen05.wait::ld.sync.aligned;" ::: "memory")
#define TC_FENCE_AFTER() asm volatile("tcgen05.fence::after_thread_sync;" ::: "memory")
#define FENCE_ASYNC()    asm volatile("fence.proxy.async.shared::cta;" ::: "memory")
#define MBAR_WAIT(mbar, par) do {                                              \
    uint32_t _m = (mbar), _p = (par);                                          \
    asm volatile(                                                              \
        "{\n\t.reg .pred P1;\n\t"                                             \
        "WL_%=:\n\t"                                                          \
        "mbarrier.try_wait.parity.acquire.cta.shared::cta.b64 P1, [%0], %1, 0x989680;\n\t" \
        "@P1 bra.uni WD_%=;\n\t"                                              \
        "bra.uni WL_%=;\n\t"                                                  \
        "WD_%=:\n\t}"                                                         \
        :: "r"(_m), "r"(_p) : "memory");                                       \
} while (0)
#define TC_LD_X32(r, a)                                                        \
    asm volatile("tcgen05.ld.sync.aligned.32x32b.x32.b32 "                     \
        "{%0,%1,%2,%3,%4,%5,%6,%7,%8,%9,%10,%11,%12,%13,%14,%15,"              \
        "%16,%17,%18,%19,%20,%21,%22,%23,%24,%25,%26,%27,%28,%29,%30,%31}, [%32];" \
        : "=r"((r)[0]),"=r"((r)[1]),"=r"((r)[2]),"=r"((r)[3]),                  \
          "=r"((r)[4]),"=r"((r)[5]),"=r"((r)[6]),"=r"((r)[7]),                  \
          "=r"((r)[8]),"=r"((r)[9]),"=r"((r)[10]),"=r"((r)[11]),                \
          "=r"((r)[12]),"=r"((r)[13]),"=r"((r)[14]),"=r"((r)[15]),              \
          "=r"((r)[16]),"=r"((r)[17]),"=r"((r)[18]),"=r"((r)[19]),              \
          "=r"((r)[20]),"=r"((r)[21]),"=r"((r)[22]),"=r"((r)[23]),              \
          "=r"((r)[24]),"=r"((r)[25]),"=r"((r)[26]),"=r"((r)[27]),              \
          "=r"((r)[28]),"=r"((r)[29]),"=r"((r)[30]),"=r"((r)[31])               \
        : "r"(a))

__device__ __forceinline__ void tma2d(uint32_t smem, const void* tmap,
                                      int x, int y, uint32_t mbar) {
    asm volatile(
        "cp.async.bulk.tensor.2d.shared::cta.global.tile.mbarrier::complete_tx::bytes "
        "[%0], [%1, {%2, %3}], [%4];"
        :: "r"(smem), "l"(tmap), "r"(x), "r"(y), "r"(mbar) : "memory");
}

// =================================================================
// TMA GEMMs, BM=128 x BN=256 (round-12 shell, best known): per stage
// A(16KB)+B0(16KB)+B1(16KB); 8 MMAs into D0/D1. 2 stages, 2 CTAs/SM.
// gemm2: split-K=4 for 2x active CTAs (512) -> pipeline overlap + tail.
// =================================================================
__global__ void __launch_bounds__(NTH, 2)
gemm1_tma_kernel(const __grid_constant__ CUtensorMap mapA,
                 const __grid_constant__ CUtensorMap mapB) {
    const int e = blockIdx.z;
    const int ne = g_count[e];
    const int row0 = blockIdx.y * 128;
    if (row0 >= ne) return;
    const int col0 = blockIdx.x * 128;   // 128 gate + 128 up cols

    extern __shared__ char dynsm[];
    __shared__ uint32_t s_tmem;
    __shared__ __align__(8) uint64_t s_full[2], s_mma[2];

    char* sm_c = (char*)(((uintptr_t)dynsm + 1023) & ~(uintptr_t)1023);
    const uint32_t sm_u = smem_u32(sm_c);

    const int tid = threadIdx.x, warp = tid >> 5, lane = tid & 31;
    if (tid < 2) MBAR_INIT(smem_u32(&s_full[tid]), 1);
    else if (tid < 4) MBAR_INIT(smem_u32(&s_mma[tid - 2]), 1);
    if (warp == 0) { TC_ALLOC(smem_u32(&s_tmem), 256); TC_RELINQ(); }
    __syncthreads();
    const uint32_t tmem = s_tmem;

    const int aY  = e * TOKENS + row0;
    const int bYg = e * (2 * INTER) + col0;
    const int bYu = e * (2 * INTER) + INTER + col0;

    if (warp == 0 && elect_one()) {
        uint32_t fullu[2], mmau[2];
#pragma unroll
        for (int i = 0; i < 2; i++) { fullu[i] = smem_u32(&s_full[i]); mmau[i] = smem_u32(&s_mma[i]); }

        auto fill = [&](int st) {
            int sl = st & 1;
            uint32_t base = sm_u + sl * STG_BYTES;
            MBAR_EXPECT_TX(fullu[sl], STG_BYTES);
            tma2d(base,                  &mapA, st * BK, aY,  fullu[sl]);
            tma2d(base + TILE_BYTES,     &mapB, st * BK, bYg, fullu[sl]);
            tma2d(base + 2 * TILE_BYTES, &mapB, st * BK, bYu, fullu[sl]);
        };

        fill(0); fill(1);
        const int NS = HIDDEN / BK;  // 64
        for (int s = 0; s < NS; s++) {
            MBAR_WAIT(fullu[s & 1], (s >> 1) & 1);
            uint32_t base = sm_u + (s & 1) * STG_BYTES;
            uint64_t ad  = mkdesc(base);
            uint64_t bd0 = mkdesc(base + TILE_BYTES);
            uint64_t bd1 = mkdesc(base + 2 * TILE_BYTES);
#pragma unroll
            for (int k = 0; k < 4; k++)
                mma_ss_tf32(tmem, ad + 2 * k, bd0 + 2 * k, MMA_IDESC, !(s == 0 && k == 0));
#pragma unroll
            for (int k = 0; k < 4; k++)
                mma_ss_tf32(tmem + 128, ad + 2 * k, bd1 + 2 * k, MMA_IDESC, !(s == 0 && k == 0));
            TC_COMMIT(mmau[s & 1]);
            if (s + 2 < NS) {
                MBAR_WAIT(mmau[s & 1], (s >> 1) & 1);
                fill(s + 2);
            }
        }
        MBAR_WAIT(mmau[(NS - 1) & 1], ((NS - 1) >> 1) & 1);
    }
    __syncthreads();
    TC_FENCE_AFTER();

    // epilogue: act = silu(g*SCALE)*(u*SCALE); 2x 32-col passes per warp
    {
        const int sub = warp & 3, half = warp >> 2;
        const int slot = row0 + sub * 32 + lane;
        float* dstb = (slot < ne)
            ? g_act + ((size_t)e * TOKENS + slot) * INTER + col0 : nullptr;
#pragma unroll
        for (int pass = 0; pass < 2; pass++) {
            const int coloff = half * 64 + pass * 32;
            uint32_t gr[32], ur[32];
            TC_LD_X32(gr, tmem + coloff);         // D0 = gate
            TC_LD_X32(ur, tmem + 128 + coloff);   // D1 = up
            TC_WAIT_LD();
            if (dstb) {
#pragma unroll
                for (int c = 0; c < 32; c += 4) {
                    float4 ov;
#pragma unroll
                    for (int q = 0; q < 4; q++) {
                        float gg = __uint_as_float(gr[c + q]) * SCALE;
                        float uu = __uint_as_float(ur[c + q]) * SCALE;
                        (&ov.x)[q] = rtf(gg / (1.f + __expf(-gg)) * uu);
                    }
                    *reinterpret_cast<float4*>(dstb + coloff + c) = ov;
                }
            }
        }
    }
    __syncthreads();
    if (warp == 0) TC_DEALLOC(tmem, 256);
}

__global__ void __launch_bounds__(NTH, 2)
gemm2_tma_kernel(const __grid_constant__ CUtensorMap mapA,
                 const __grid_constant__ CUtensorMap mapB,
                 float* __restrict__ out) {
    const int e  = blockIdx.z >> 2;          // split-K = 4
    const int ks = blockIdx.z & 3;
    const int ne = g_count[e];
    const int row0 = blockIdx.y * 128;
    if (row0 >= ne) return;
    const int col0 = blockIdx.x * 256;
    const int kbase = ks * (INTER / 4);

    extern __shared__ char dynsm[];
    __shared__ uint32_t s_tmem;
    __shared__ __align__(8) uint64_t s_full[2], s_mma[2];

    char* sm_c = (char*)(((uintptr_t)dynsm + 1023) & ~(uintptr_t)1023);
    const uint32_t sm_u = smem_u32(sm_c);

    const int tid = threadIdx.x, warp = tid >> 5, lane = tid & 31;
    if (tid < 2) MBAR_INIT(smem_u32(&s_full[tid]), 1);
    else if (tid < 4) MBAR_INIT(smem_u32(&s_mma[tid - 2]), 1);
    if (warp == 0) { TC_ALLOC(smem_u32(&s_tmem), 256); TC_RELINQ(); }
    __syncthreads();
    const uint32_t tmem = s_tmem;

    const int aY = e * TOKENS + row0;
    const int bY0 = e * HIDDEN + col0;
    const int bY1 = e * HIDDEN + col0 + 128;

    if (warp == 0 && elect_one()) {
        uint32_t fullu[2], mmau[2];
#pragma unroll
        for (int i = 0; i < 2; i++) { fullu[i] = smem_u32(&s_full[i]); mmau[i] = smem_u32(&s_mma[i]); }

        auto fill = [&](int st) {
            int sl = st & 1;
            uint32_t base = sm_u + sl * STG_BYTES;
            MBAR_EXPECT_TX(fullu[sl], STG_BYTES);
            tma2d(base,                  &mapA, kbase + st * BK, aY,  fullu[sl]);
            tma2d(base + TILE_BYTES,     &mapB, kbase + st * BK, bY0, fullu[sl]);
            tma2d(base + 2 * TILE_BYTES, &mapB, kbase + st * BK, bY1, fullu[sl]);
        };

        fill(0); fill(1);
        const int NS = (INTER / 4) / BK;  // 32
        for (int s = 0; s < NS; s++) {
            MBAR_WAIT(fullu[s & 1], (s >> 1) & 1);
            uint32_t base = sm_u + (s & 1) * STG_BYTES;
            uint64_t ad  = mkdesc(base);
            uint64_t bd0 = mkdesc(base + TILE_BYTES);
            uint64_t bd1 = mkdesc(base + 2 * TILE_BYTES);
#pragma unroll
            for (int k = 0; k < 4; k++)
                mma_ss_tf32(tmem, ad + 2 * k, bd0 + 2 * k, MMA_IDESC, !(s == 0 && k == 0));
#pragma unroll
            for (int k = 0; k < 4; k++)
                mma_ss_tf32(tmem + 128, ad + 2 * k, bd1 + 2 * k, MMA_IDESC, !(s == 0 && k == 0));
            TC_COMMIT(mmau[s & 1]);
            if (s + 2 < NS) {
                MBAR_WAIT(mmau[s & 1], (s >> 1) & 1);
                fill(s + 2);
            }
        }
        MBAR_WAIT(mmau[(NS - 1) & 1], ((NS - 1) >> 1) & 1);
    }
    __syncthreads();
    TC_FENCE_AFTER();

    // epilogue: out[token] += (w*SCALE) * D over 256 cols; 2 blocks x 64/warp
    {
        const int sub = warp & 3, half = warp >> 2;
        const int slot = row0 + sub * 32 + lane;
        int tok = 0; float w = 0.f;
        if (slot < ne) { tok = g_tok[e][slot]; w = g_w[e][slot] * SCALE; }
#pragma unroll
        for (int blk = 0; blk < 2; blk++) {
            uint32_t d0[32], d1[32];
            TC_LD_X32(d0, tmem + blk * 128 + half * 64);
            TC_LD_X32(d1, tmem + blk * 128 + half * 64 + 32);
            TC_WAIT_LD();
            if (slot < ne) {
                float* o = out + (size_t)tok * HIDDEN + col0 + blk * 128 + half * 64;
#pragma unroll
                for (int c = 0; c < 32; c++) atomicAdd(o + c, w * __uint_as_float(d0[c]));
#pragma unroll
                for (int c = 0; c < 32; c++) atomicAdd(o + 32 + c, w * __uint_as_float(d1[c]));
            }
        }
    }
    __syncthreads();
    if (warp == 0) TC_DEALLOC(tmem, 256);
}

// =================================================================
// cp.async fallback GEMMs — round-9 kernels (known-good path)
// =================================================================
template <int NS, typename BRowOf>
__device__ __forceinline__ void mma_mainloop(
    uint32_t smA_u, uint32_t smB_u,
    const float* aBase, size_t aStride,
    uint32_t tmem, const uint32_t* mb, BRowOf&& bRowOf)
{
    const int tid = threadIdx.x, warp = tid >> 5;

    auto fill = [&](int st) {
        uint32_t dA = smA_u + (st % 3) * TILE_BYTES;
        uint32_t dB = smB_u + (st % 3) * TILE_BYTES;
#pragma unroll
        for (int j = 0; j < 4; j++) {
            int i = tid + NTH * j;
            int row = i >> 3, c = i & 7;
            uint32_t so = swz((uint32_t)(row * 128 + c * 16));
            cp16(dA + so, aBase + (size_t)row * aStride + st * BK + c * 4);
            cp16(dB + so, bRowOf(row) + st * BK + c * 4);
        }
        cp_commit();
    };

    fill(0); fill(1);

    for (int s = 0; s < NS; s++) {
        if (s < NS - 1) cp_wait<1>();
        else            cp_wait<0>();
        FENCE_ASYNC();
        __syncthreads();

        if (warp == 0 && elect_one()) {
            uint64_t ad = mkdesc(smA_u + (s % 3) * TILE_BYTES);
            uint64_t bd = mkdesc(smB_u + (s % 3) * TILE_BYTES);
#pragma unroll
            for (int k = 0; k < 4; k++)
                mma_ss_tf32(tmem, ad + 2 * k, bd + 2 * k, MMA_IDESC, !(s == 0 && k == 0));
            TC_COMMIT(mb[s % 3]);
        }

        if (s + 2 < NS) {
            if (s >= 1) MBAR_WAIT(mb[(s - 1) % 3], (((s - 1) / 3) & 1));
            fill(s + 2);
        }
    }
    MBAR_WAIT(mb[(NS - 1) % 3], (((NS - 1) / 3) & 1));
    TC_FENCE_AFTER();
}

__global__ void __launch_bounds__(NTH, 2)
gemm1_kernel(const float* __restrict__ W13) {
    const int e = blockIdx.z;
    const int ne = g_count[e];
    const int row0 = blockIdx.y * 128;
    if (row0 >= ne) return;
    const int col0 = blockIdx.x * 64;

    extern __shared__ char dynsm[];
    __shared__ uint32_t s_tmem;
    __shared__ __align__(8) uint64_t s_mbar[3];
    __shared__ uint32_t s_mb[3];

    char* smA_c = (char*)(((uintptr_t)dynsm + 1023) & ~(uintptr_t)1023);
    const uint32_t smA_u = smem_u32(smA_c);
    const uint32_t smB_u = smA_u + 3 * TILE_BYTES;

    const int tid = threadIdx.x, warp = tid >> 5, lane = tid & 31;
    if (tid < 3) { MBAR_INIT(smem_u32(&s_mbar[tid]), 1); s_mb[tid] = smem_u32(&s_mbar[tid]); }
    if (warp == 0) { TC_ALLOC(smem_u32(&s_tmem), 128); TC_RELINQ(); }
    __syncthreads();
    const uint32_t tmem = s_tmem;

    const float* aBase = g_xg + ((size_t)e * TOKENS + row0) * HIDDEN;
    const float* wBase = W13 + (size_t)e * (2 * INTER) * HIDDEN;

    auto bRowOf = [&](int row) -> const float* {
        int grow = (row < 64) ? (col0 + row) : (INTER + col0 + row - 64);
        return wBase + (size_t)grow * HIDDEN;
    };

    mma_mainloop<HIDDEN / BK>(smA_u, smB_u, aBase, HIDDEN, tmem, s_mb, bRowOf);

    {
        const int sub = warp & 3, half = warp >> 2;
        uint32_t gr[32], ur[32];
        TC_LD_X32(gr, tmem + 32 * half);
        TC_LD_X32(ur, tmem + 64 + 32 * half);
        TC_WAIT_LD();
        const int slot = row0 + sub * 32 + lane;
        if (slot < ne) {
            float* dst = g_act + ((size_t)e * TOKENS + slot) * INTER + col0 + 32 * half;
#pragma unroll
            for (int c = 0; c < 32; c += 4) {
                float4 ov;
#pragma unroll
                for (int q = 0; q < 4; q++) {
                    float gg = __uint_as_float(gr[c + q]) * SCALE;
                    float uu = __uint_as_float(ur[c + q]) * SCALE;
                    (&ov.x)[q] = rtf(gg / (1.f + __expf(-gg)) * uu);
                }
                *reinterpret_cast<float4*>(dst + c) = ov;
            }
        }
    }
    __syncthreads();
    if (warp == 0) TC_DEALLOC(tmem, 128);
}

__global__ void __launch_bounds__(NTH, 2)
gemm2_kernel(const float* __restrict__ W2, float* __restrict__ out) {
    const int e  = blockIdx.z >> 1;
    const int ks = blockIdx.z & 1;
    const int ne = g_count[e];
    const int row0 = blockIdx.y * 128;
    if (row0 >= ne) return;
    const int col0 = blockIdx.x * 128;
    const int kbase = ks * (INTER / 2);

    extern __shared__ char dynsm[];
    __shared__ uint32_t s_tmem;
    __shared__ __align__(8) uint64_t s_mbar[3];
    __shared__ uint32_t s_mb[3];

    char* smA_c = (char*)(((uintptr_t)dynsm + 1023) & ~(uintptr_t)1023);
    const uint32_t smA_u = smem_u32(smA_c);
    const uint32_t smB_u = smA_u + 3 * TILE_BYTES;

    const int tid = threadIdx.x, warp = tid >> 5, lane = tid & 31;
    if (tid < 3) { MBAR_INIT(smem_u32(&s_mbar[tid]), 1); s_mb[tid] = smem_u32(&s_mbar[tid]); }
    if (warp == 0) { TC_ALLOC(smem_u32(&s_tmem), 128); TC_RELINQ(); }
    __syncthreads();
    const uint32_t tmem = s_tmem;

    const float* aBase = g_act + ((size_t)e * TOKENS + row0) * INTER + kbase;
    const float* bBase = W2 + (size_t)e * HIDDEN * INTER + kbase;

    auto bRowOf = [&](int row) -> const float* {
        return bBase + (size_t)(col0 + row) * INTER;
    };

    mma_mainloop<(INTER / 2) / BK>(smA_u, smB_u, aBase, INTER, tmem, s_mb, bRowOf);

    {
        const int sub = warp & 3, half = warp >> 2;
        uint32_t d0[32], d1[32];
        TC_LD_X32(d0, tmem + 64 * half);
        TC_LD_X32(d1, tmem + 64 * half + 32);
        TC_WAIT_LD();
        const int slot = row0 + sub * 32 + lane;
        if (slot < ne) {
            const int tok = g_tok[e][slot];
            const float w = g_w[e][slot] * SCALE;
            float* o = out + (size_t)tok * HIDDEN + col0 + 64 * half;
#pragma unroll
            for (int c = 0; c < 32; c++) atomicAdd(o + c, w * __uint_as_float(d0[c]));
#pragma unroll
            for (int c = 0; c < 32; c++) atomicAdd(o + 32 + c, w * __uint_as_float(d1[c]));
        }
    }
    __syncthreads();
    if (warp == 0) TC_DEALLOC(tmem, 128);
}

#else
// =================================================================
// Fallback (compute_103 PTX pass only; never executes on sm_103a device)
// =================================================================
__device__ __forceinline__ float trunc_tf32(float f) {
    return __uint_as_float(__float_as_uint(f) & 0xFFFFE000u);
}

__global__ void __launch_bounds__(NTH, 2)
gemm1_kernel(const float* __restrict__ W13) {
    const int e = blockIdx.z;
    const int ne = g_count[e];
    const int row0 = blockIdx.y * 128;
    if (row0 >= ne) return;
    const int col0 = blockIdx.x * 64;
    const float* wBase = W13 + (size_t)e * (2 * INTER) * HIDDEN;

    for (int idx = threadIdx.x; idx < 128 * 64; idx += NTH) {
        int rr = idx >> 6, cc = idx & 63;
        int slot = row0 + rr;
        if (slot >= ne) continue;
        const float* a = g_xg + ((size_t)e * TOKENS + slot) * HIDDEN;
        const float* bg = wBase + (size_t)(col0 + cc) * HIDDEN;
        const float* bu = wBase + (size_t)(INTER + col0 + cc) * HIDDEN;
        float sg = 0.f, su = 0.f;
        for (int k = 0; k < HIDDEN; k++) {
            float av = a[k];
            sg += av * trunc_tf32(bg[k]);
            su += av * trunc_tf32(bu[k]);
        }
        sg *= SCALE; su *= SCALE;
        float act = sg / (1.f + __expf(-sg)) * su;
        g_act[((size_t)e * TOKENS + slot) * INTER + col0 + cc] = rtf(act);
    }
}

__global__ void __launch_bounds__(NTH, 2)
gemm2_kernel(const float* __restrict__ W2, float* __restrict__ out) {
    const int e  = blockIdx.z >> 1;
    const int ks = blockIdx.z & 1;
    const int ne = g_count[e];
    const int row0 = blockIdx.y * 128;
    if (row0 >= ne) return;
    const int col0 = blockIdx.x * 128;
    const int kbase = ks * (INTER / 2);
    const float* bBase = W2 + (size_t)e * HIDDEN * INTER;

    for (int idx = threadIdx.x; idx < 128 * 128; idx += NTH) {
        int rr = idx >> 7, cc = idx & 127;
        int slot = row0 + rr;
        if (slot >= ne) continue;
        const float* a = g_act + ((size_t)e * TOKENS + slot) * INTER + kbase;
        const float* b = bBase + (size_t)(col0 + cc) * INTER + kbase;
        float s = 0.f;
        for (int k = 0; k < INTER / 2; k++) s += a[k] * trunc_tf32(b[k]);
        atomicAdd(&out[(size_t)g_tok[e][slot] * HIDDEN + col0 + cc],
                  g_w[e][slot] * SCALE * s);
    }
}

__global__ void __launch_bounds__(NTH, 2)
gemm1_tma_kernel(const __grid_constant__ CUtensorMap mapA,
                 const __grid_constant__ CUtensorMap mapB) {}
__global__ void __launch_bounds__(NTH, 2)
gemm2_tma_kernel(const __grid_constant__ CUtensorMap mapA,
                 const __grid_constant__ CUtensorMap mapB,
                 float* __restrict__ out) {}
#endif  // USE_TC

// ---------------- host: tensormap construction via dlopen ----------------
typedef CUresult (*EncodeTiledFn)(
    CUtensorMap*, CUtensorMapDataType, cuuint32_t, void*,
    const cuuint64_t*, const cuuint64_t*, const cuuint32_t*, const cuuint32_t*,
    CUtensorMapInterleave, CUtensorMapSwizzle, CUtensorMapL2promotion,
    CUtensorMapFloatOOBfill);

static bool make_map2d(EncodeTiledFn fn, CUtensorMap* m, void* base,
                       uint64_t width, uint64_t height, uint32_t box0, uint32_t box1) {
    cuuint64_t dims[2] = {width, height};
    cuuint64_t strides[1] = {width * sizeof(float)};
    cuuint32_t box[2] = {box0, box1};
    cuuint32_t elemstr[2] = {1, 1};
    CUresult r = fn(m, CU_TENSOR_MAP_DATA_TYPE_FLOAT32, 2, base,
                    dims, strides, box, elemstr,
                    CU_TENSOR_MAP_INTERLEAVE_NONE, CU_TENSOR_MAP_SWIZZLE_128B,
                    CU_TENSOR_MAP_L2_PROMOTION_L2_128B,
                    CU_TENSOR_MAP_FLOAT_OOB_FILL_NONE);
    return r == CUDA_SUCCESS;
}

// ---------------- launch ----------------
extern "C" void kernel_launch(void* const* d_in, const int* in_sizes, int n_in,
                              void* d_out, int out_size) {
    const float* X      = (const float*)d_in[0];
    const float* logits = (const float*)d_in[1];
    const float* W13    = (const float*)d_in[2];
    const float* W2     = (const float*)d_in[3];
    float* out = (float*)d_out;

    cudaFuncSetAttribute(gemm1_kernel, cudaFuncAttributeMaxDynamicSharedMemorySize, DYN_SMEM);
    cudaFuncSetAttribute(gemm2_kernel, cudaFuncAttributeMaxDynamicSharedMemorySize, DYN_SMEM);
    cudaFuncSetAttribute(gemm1_tma_kernel, cudaFuncAttributeMaxDynamicSharedMemorySize, DYN_SMEM);
    cudaFuncSetAttribute(gemm2_tma_kernel, cudaFuncAttributeMaxDynamicSharedMemorySize, DYN_SMEM);

    bool tma_ok = false;
    CUtensorMap mA1, mB1, mA2, mB2;
    {
        void* h = dlopen("libcuda.so.1", RTLD_NOW | RTLD_GLOBAL);
        if (!h) h = dlopen("libcuda.so", RTLD_NOW | RTLD_GLOBAL);
        EncodeTiledFn fn = h ? (EncodeTiledFn)dlsym(h, "cuTensorMapEncodeTiled") : nullptr;
        void *p_xg = nullptr, *p_act = nullptr;
        if (fn &&
            cudaGetSymbolAddress(&p_xg, g_xg) == cudaSuccess &&
            cudaGetSymbolAddress(&p_act, g_act) == cudaSuccess) {
            tma_ok =
                make_map2d(fn, &mA1, p_xg,        HIDDEN, (uint64_t)NEXP * TOKENS,     32, 128) &&
                make_map2d(fn, &mB1, (void*)W13,  HIDDEN, (uint64_t)NEXP * 2 * INTER,  32, 128) &&
                make_map2d(fn, &mA2, p_act,       INTER,  (uint64_t)NEXP * TOKENS,     32, 128) &&
                make_map2d(fn, &mB2, (void*)W2,   INTER,  (uint64_t)NEXP * HIDDEN,     32, 128);
        }
    }

    zero_kernel<<<(TOKENS * HIDDEN / 4) / 256, 256>>>(out);
    router_kernel<<<(TOKENS + 255) / 256, 256>>>(logits);

    dim3 gg(TOKENS, NEXP);
    gather_kernel<<<gg, 256>>>(X);

    if (tma_ok) {
        dim3 g1(INTER / 128, TOKENS / 128, NEXP);          // BM=128, BN=256 (g+u)
        dim3 g2(HIDDEN / 256, TOKENS / 128, NEXP * 4);     // BM=128, BN=256, splitK=4
        gemm1_tma_kernel<<<g1, NTH, DYN_SMEM>>>(mA1, mB1);
        gemm2_tma_kernel<<<g2, NTH, DYN_SMEM>>>(mA2, mB2, out);
    } else {
        dim3 g1(INTER / 64, TOKENS / 128, NEXP);
        dim3 g2(HIDDEN / 128, TOKENS / 128, NEXP * 2);
        gemm1_kernel<<<g1, NTH, DYN_SMEM>>>(W13);
        gemm2_kernel<<<g2, NTH, DYN_SMEM>>>(W2, out);
    }
}

// round 16
// speedup vs baseline: 1.3938x; 1.1935x over previous
#include <cuda_runtime.h>
#include <cuda.h>
#include <dlfcn.h>
#include <cstdint>
#include <cstddef>
#include <cstring>

#define TOKENS 1024
#define HIDDEN 2048
#define INTER  4096
#define NEXP   8
#define NTH    256
#define BK     32
#define TILE_BYTES 16384
#define STG_BYTES  49152                  // A + B0 + B1 per stage
#define DYN_SMEM   (2 * STG_BYTES + 1024) // 2 stages -> 2 CTAs/SM
// Compensation for HW fp32->tf32 truncation of B (mean bias ~2^-11 toward zero)
#define SCALE 1.00048828125f

#if defined(__CUDA_ARCH__) && defined(__CUDA_ARCH_FEAT_SM103_ALL)
#define USE_TC 1
#else
#define USE_TC 0
#endif

// ---------------- device scratch ----------------
__device__ int   g_count[NEXP];
__device__ int   g_tok[NEXP][TOKENS];
__device__ float g_w[NEXP][TOKENS];
__device__ float g_xg[(size_t)NEXP * TOKENS * HIDDEN];   // gathered + tf32-rounded X
__device__ float g_act[(size_t)NEXP * TOKENS * INTER];   // tf32-rounded activations

// ---------------- common helpers ----------------
__device__ __forceinline__ uint32_t f2tf32(float f) {
    uint32_t u;
    asm("cvt.rna.tf32.f32 %0, %1;" : "=r"(u) : "f"(f));
    return u;
}
__device__ __forceinline__ float rtf(float f) { return __uint_as_float(f2tf32(f)); }
__device__ __forceinline__ uint32_t smem_u32(const void* p) {
    uint32_t a;
    asm("{ .reg .u64 t; cvta.to.shared.u64 t, %1; cvt.u32.u64 %0, t; }" : "=r"(a) : "l"(p));
    return a;
}
__device__ __forceinline__ void cp16(uint32_t dst, const float* src) {
    asm volatile("cp.async.cg.shared.global [%0], [%1], 16;\n" :: "r"(dst), "l"(src));
}
__device__ __forceinline__ void cp_commit() { asm volatile("cp.async.commit_group;\n"); }
template <int N> __device__ __forceinline__ void cp_wait() {
    asm volatile("cp.async.wait_group %0;\n" :: "n"(N) : "memory");
}

// ---------------- kernel 0: zero out + counts ----------------
__global__ void zero_kernel(float* __restrict__ out) {
    int i = blockIdx.x * blockDim.x + threadIdx.x;
    reinterpret_cast<float4*>(out)[i] = make_float4(0.f, 0.f, 0.f, 0.f);
    if (blockIdx.x == 0 && threadIdx.x < NEXP) g_count[threadIdx.x] = 0;
}

// ---------------- kernel 1: router ----------------
__global__ void router_kernel(const float* __restrict__ logits) {
    int t = blockIdx.x * blockDim.x + threadIdx.x;
    if (t >= TOKENS) return;
    float l[NEXP];
#pragma unroll
    for (int j = 0; j < NEXP; j++) l[j] = logits[t * NEXP + j];
    int i0 = 0;
#pragma unroll
    for (int j = 1; j < NEXP; j++) if (l[j] > l[i0]) i0 = j;
    int i1 = -1;
#pragma unroll
    for (int j = 0; j < NEXP; j++) {
        if (j == i0) continue;
        if (i1 < 0 || l[j] > l[i1]) i1 = j;
    }
    float e1 = __expf(l[i1] - l[i0]);
    float w1 = e1 / (1.f + e1);
    float w0 = 1.f / (1.f + e1);
    int p0 = atomicAdd(&g_count[i0], 1);
    g_tok[i0][p0] = t;  g_w[i0][p0] = w0;
    int p1 = atomicAdd(&g_count[i1], 1);
    g_tok[i1][p1] = t;  g_w[i1][p1] = w1;
}

// ---------------- kernel 2: gather + tf32-round X ----------------
__global__ void gather_kernel(const float* __restrict__ X) {
    int row = blockIdx.x, e = blockIdx.y;
    if (row >= g_count[e]) return;
    int tok = g_tok[e][row];
    const float4* src = reinterpret_cast<const float4*>(X + (size_t)tok * HIDDEN);
    float4* dst = reinterpret_cast<float4*>(g_xg + ((size_t)e * TOKENS + row) * HIDDEN);
#pragma unroll
    for (int j = 0; j < 2; j++) {
        float4 v = src[threadIdx.x + 256 * j];
        v.x = rtf(v.x); v.y = rtf(v.y); v.z = rtf(v.z); v.w = rtf(v.w);
        dst[threadIdx.x + 256 * j] = v;
    }
}

#if USE_TC
// =================================================================
// tcgen05 helpers
// =================================================================
#define MMA_IDESC ((1u<<4)|(2u<<7)|(2u<<10)|((128u/8)<<17)|((128u/16)<<24))

__device__ __forceinline__ uint32_t elect_one() {
    uint32_t p;
    asm volatile("{\n\t.reg .pred p;\n\telect.sync _|p, 0xFFFFFFFF;\n\tselp.b32 %0, 1, 0, p;\n\t}" : "=r"(p));
    return p;
}
__device__ __forceinline__ uint32_t swz(uint32_t o) { return o ^ ((o >> 3) & 0x70); }

static constexpr uint64_t DESC_SW128 =
    (2ull << 61) | (1ull << 46) | (64ull << 32) | (1ull << 16);
__device__ __forceinline__ uint64_t mkdesc(uint32_t addr) {
    return DESC_SW128 | ((uint64_t)(addr >> 4) & 0x3FFF);
}
__device__ __forceinline__ void mma_ss_tf32(uint32_t d, uint64_t ad, uint64_t bd,
                                            uint32_t idesc, bool en) {
    uint32_t e = en ? 1u : 0u;
    asm volatile(
        "{\n\t.reg .pred p;\n\tsetp.ne.u32 p, %4, 0;\n\t"
        "tcgen05.mma.cta_group::1.kind::tf32 [%0], %1, %2, %3, p;\n\t}"
        :: "r"(d), "l"(ad), "l"(bd), "r"(idesc), "r"(e) : "memory");
}
#define MBAR_INIT(a, c)  asm volatile("mbarrier.init.shared.b64 [%0], %1;" :: "r"(a), "r"(c) : "memory")
#define MBAR_EXPECT_TX(a, n) asm volatile("mbarrier.arrive.expect_tx.shared.b64 _, [%0], %1;" :: "r"(a), "r"(n) : "memory")
#define TC_COMMIT(a)     asm volatile("tcgen05.commit.cta_group::1.mbarrier::arrive::one.shared::cluster.b64 [%0];" :: "r"(a) : "memory")
#define TC_ALLOC(a, n)   asm volatile("tcgen05.alloc.cta_group::1.sync.aligned.shared::cta.b32 [%0], %1;" :: "r"(a), "r"(n) : "memory")
#define TC_RELINQ()      asm volatile("tcgen05.relinquish_alloc_permit.cta_group::1.sync.aligned;")
#define TC_DEALLOC(t, n) asm volatile("tcgen05.dealloc.cta_group::1.sync.aligned.b32 %0, %1;" :: "r"(t), "r"(n))
#define TC_WAIT_LD()     asm volatile("tcgen05.wait::ld.sync.aligned;" ::: "memory")
#define TC_FENCE_AFTER() asm volatile("tcgen05.fence::after_thread_sync;" ::: "memory")
#define FENCE_ASYNC()    asm volatile("fence.proxy.async.shared::cta;" ::: "memory")
#define MBAR_WAIT(mbar, par) do {                                              \
    uint32_t _m = (mbar), _p = (par);                                          \
    asm volatile(                                                              \
        "{\n\t.reg .pred P1;\n\t"                                             \
        "WL_%=:\n\t"                                                          \
        "mbarrier.try_wait.parity.acquire.cta.shared::cta.b64 P1, [%0], %1, 0x989680;\n\t" \
        "@P1 bra.uni WD_%=;\n\t"                                              \
        "bra.uni WL_%=;\n\t"                                                  \
        "WD_%=:\n\t}"                                                         \
        :: "r"(_m), "r"(_p) : "memory");                                       \
} while (0)
#define TC_LD_X32(r, a)                                                        \
    asm volatile("tcgen05.ld.sync.aligned.32x32b.x32.b32 "                     \
        "{%0,%1,%2,%3,%4,%5,%6,%7,%8,%9,%10,%11,%12,%13,%14,%15,"              \
        "%16,%17,%18,%19,%20,%21,%22,%23,%24,%25,%26,%27,%28,%29,%30,%31}, [%32];" \
        : "=r"((r)[0]),"=r"((r)[1]),"=r"((r)[2]),"=r"((r)[3]),                  \
          "=r"((r)[4]),"=r"((r)[5]),"=r"((r)[6]),"=r"((r)[7]),                  \
          "=r"((r)[8]),"=r"((r)[9]),"=r"((r)[10]),"=r"((r)[11]),                \
          "=r"((r)[12]),"=r"((r)[13]),"=r"((r)[14]),"=r"((r)[15]),              \
          "=r"((r)[16]),"=r"((r)[17]),"=r"((r)[18]),"=r"((r)[19]),              \
          "=r"((r)[20]),"=r"((r)[21]),"=r"((r)[22]),"=r"((r)[23]),              \
          "=r"((r)[24]),"=r"((r)[25]),"=r"((r)[26]),"=r"((r)[27]),              \
          "=r"((r)[28]),"=r"((r)[29]),"=r"((r)[30]),"=r"((r)[31])               \
        : "r"(a))

__device__ __forceinline__ void tma2d(uint32_t smem, const void* tmap,
                                      int x, int y, uint32_t mbar) {
    asm volatile(
        "cp.async.bulk.tensor.2d.shared::cta.global.tile.mbarrier::complete_tx::bytes "
        "[%0], [%1, {%2, %3}], [%4];"
        :: "r"(smem), "l"(tmap), "r"(x), "r"(y), "r"(mbar) : "memory");
}

// =================================================================
// TMA GEMMs, BM=128 x BN=256 (round-12 configuration — the measured
// optimum of this family): per stage A(16KB)+B0(16KB)+B1(16KB); 8 MMAs
// into D0/D1. 2 stages, 2 CTAs/SM; gemm2 split-K=2.
// =================================================================
__global__ void __launch_bounds__(NTH, 2)
gemm1_tma_kernel(const __grid_constant__ CUtensorMap mapA,
                 const __grid_constant__ CUtensorMap mapB) {
    const int e = blockIdx.z;
    const int ne = g_count[e];
    const int row0 = blockIdx.y * 128;
    if (row0 >= ne) return;
    const int col0 = blockIdx.x * 128;   // 128 gate + 128 up cols

    extern __shared__ char dynsm[];
    __shared__ uint32_t s_tmem;
    __shared__ __align__(8) uint64_t s_full[2], s_mma[2];

    char* sm_c = (char*)(((uintptr_t)dynsm + 1023) & ~(uintptr_t)1023);
    const uint32_t sm_u = smem_u32(sm_c);

    const int tid = threadIdx.x, warp = tid >> 5, lane = tid & 31;
    if (tid < 2) MBAR_INIT(smem_u32(&s_full[tid]), 1);
    else if (tid < 4) MBAR_INIT(smem_u32(&s_mma[tid - 2]), 1);
    if (warp == 0) { TC_ALLOC(smem_u32(&s_tmem), 256); TC_RELINQ(); }
    __syncthreads();
    const uint32_t tmem = s_tmem;

    const int aY  = e * TOKENS + row0;
    const int bYg = e * (2 * INTER) + col0;
    const int bYu = e * (2 * INTER) + INTER + col0;

    if (warp == 0 && elect_one()) {
        uint32_t fullu[2], mmau[2];
#pragma unroll
        for (int i = 0; i < 2; i++) { fullu[i] = smem_u32(&s_full[i]); mmau[i] = smem_u32(&s_mma[i]); }

        auto fill = [&](int st) {
            int sl = st & 1;
            uint32_t base = sm_u + sl * STG_BYTES;
            MBAR_EXPECT_TX(fullu[sl], STG_BYTES);
            tma2d(base,                  &mapA, st * BK, aY,  fullu[sl]);
            tma2d(base + TILE_BYTES,     &mapB, st * BK, bYg, fullu[sl]);
            tma2d(base + 2 * TILE_BYTES, &mapB, st * BK, bYu, fullu[sl]);
        };

        fill(0); fill(1);
        const int NS = HIDDEN / BK;  // 64
        for (int s = 0; s < NS; s++) {
            MBAR_WAIT(fullu[s & 1], (s >> 1) & 1);
            uint32_t base = sm_u + (s & 1) * STG_BYTES;
            uint64_t ad  = mkdesc(base);
            uint64_t bd0 = mkdesc(base + TILE_BYTES);
            uint64_t bd1 = mkdesc(base + 2 * TILE_BYTES);
#pragma unroll
            for (int k = 0; k < 4; k++)
                mma_ss_tf32(tmem, ad + 2 * k, bd0 + 2 * k, MMA_IDESC, !(s == 0 && k == 0));
#pragma unroll
            for (int k = 0; k < 4; k++)
                mma_ss_tf32(tmem + 128, ad + 2 * k, bd1 + 2 * k, MMA_IDESC, !(s == 0 && k == 0));
            TC_COMMIT(mmau[s & 1]);
            if (s + 2 < NS) {
                MBAR_WAIT(mmau[s & 1], (s >> 1) & 1);
                fill(s + 2);
            }
        }
        MBAR_WAIT(mmau[(NS - 1) & 1], ((NS - 1) >> 1) & 1);
    }
    __syncthreads();
    TC_FENCE_AFTER();

    // epilogue: act = silu(g*SCALE)*(u*SCALE); 2x 32-col passes per warp
    {
        const int sub = warp & 3, half = warp >> 2;
        const int slot = row0 + sub * 32 + lane;
        float* dstb = (slot < ne)
            ? g_act + ((size_t)e * TOKENS + slot) * INTER + col0 : nullptr;
#pragma unroll
        for (int pass = 0; pass < 2; pass++) {
            const int coloff = half * 64 + pass * 32;
            uint32_t gr[32], ur[32];
            TC_LD_X32(gr, tmem + coloff);         // D0 = gate
            TC_LD_X32(ur, tmem + 128 + coloff);   // D1 = up
            TC_WAIT_LD();
            if (dstb) {
#pragma unroll
                for (int c = 0; c < 32; c += 4) {
                    float4 ov;
#pragma unroll
                    for (int q = 0; q < 4; q++) {
                        float gg = __uint_as_float(gr[c + q]) * SCALE;
                        float uu = __uint_as_float(ur[c + q]) * SCALE;
                        (&ov.x)[q] = rtf(gg / (1.f + __expf(-gg)) * uu);
                    }
                    *reinterpret_cast<float4*>(dstb + coloff + c) = ov;
                }
            }
        }
    }
    __syncthreads();
    if (warp == 0) TC_DEALLOC(tmem, 256);
}

__global__ void __launch_bounds__(NTH, 2)
gemm2_tma_kernel(const __grid_constant__ CUtensorMap mapA,
                 const __grid_constant__ CUtensorMap mapB,
                 float* __restrict__ out) {
    const int e  = blockIdx.z >> 1;          // split-K = 2 (measured optimum)
    const int ks = blockIdx.z & 1;
    const int ne = g_count[e];
    const int row0 = blockIdx.y * 128;
    if (row0 >= ne) return;
    const int col0 = blockIdx.x * 256;
    const int kbase = ks * (INTER / 2);

    extern __shared__ char dynsm[];
    __shared__ uint32_t s_tmem;
    __shared__ __align__(8) uint64_t s_full[2], s_mma[2];

    char* sm_c = (char*)(((uintptr_t)dynsm + 1023) & ~(uintptr_t)1023);
    const uint32_t sm_u = smem_u32(sm_c);

    const int tid = threadIdx.x, warp = tid >> 5, lane = tid & 31;
    if (tid < 2) MBAR_INIT(smem_u32(&s_full[tid]), 1);
    else if (tid < 4) MBAR_INIT(smem_u32(&s_mma[tid - 2]), 1);
    if (warp == 0) { TC_ALLOC(smem_u32(&s_tmem), 256); TC_RELINQ(); }
    __syncthreads();
    const uint32_t tmem = s_tmem;

    const int aY = e * TOKENS + row0;
    const int bY0 = e * HIDDEN + col0;
    const int bY1 = e * HIDDEN + col0 + 128;

    if (warp == 0 && elect_one()) {
        uint32_t fullu[2], mmau[2];
#pragma unroll
        for (int i = 0; i < 2; i++) { fullu[i] = smem_u32(&s_full[i]); mmau[i] = smem_u32(&s_mma[i]); }

        auto fill = [&](int st) {
            int sl = st & 1;
            uint32_t base = sm_u + sl * STG_BYTES;
            MBAR_EXPECT_TX(fullu[sl], STG_BYTES);
            tma2d(base,                  &mapA, kbase + st * BK, aY,  fullu[sl]);
            tma2d(base + TILE_BYTES,     &mapB, kbase + st * BK, bY0, fullu[sl]);
            tma2d(base + 2 * TILE_BYTES, &mapB, kbase + st * BK, bY1, fullu[sl]);
        };

        fill(0); fill(1);
        const int NS = (INTER / 2) / BK;  // 64
        for (int s = 0; s < NS; s++) {
            MBAR_WAIT(fullu[s & 1], (s >> 1) & 1);
            uint32_t base = sm_u + (s & 1) * STG_BYTES;
            uint64_t ad  = mkdesc(base);
            uint64_t bd0 = mkdesc(base + TILE_BYTES);
            uint64_t bd1 = mkdesc(base + 2 * TILE_BYTES);
#pragma unroll
            for (int k = 0; k < 4; k++)
                mma_ss_tf32(tmem, ad + 2 * k, bd0 + 2 * k, MMA_IDESC, !(s == 0 && k == 0));
#pragma unroll
            for (int k = 0; k < 4; k++)
                mma_ss_tf32(tmem + 128, ad + 2 * k, bd1 + 2 * k, MMA_IDESC, !(s == 0 && k == 0));
            TC_COMMIT(mmau[s & 1]);
            if (s + 2 < NS) {
                MBAR_WAIT(mmau[s & 1], (s >> 1) & 1);
                fill(s + 2);
            }
        }
        MBAR_WAIT(mmau[(NS - 1) & 1], ((NS - 1) >> 1) & 1);
    }
    __syncthreads();
    TC_FENCE_AFTER();

    // epilogue: out[token] += (w*SCALE) * D over 256 cols; 2 blocks x 64/warp
    {
        const int sub = warp & 3, half = warp >> 2;
        const int slot = row0 + sub * 32 + lane;
        int tok = 0; float w = 0.f;
        if (slot < ne) { tok = g_tok[e][slot]; w = g_w[e][slot] * SCALE; }
#pragma unroll
        for (int blk = 0; blk < 2; blk++) {
            uint32_t d0[32], d1[32];
            TC_LD_X32(d0, tmem + blk * 128 + half * 64);
            TC_LD_X32(d1, tmem + blk * 128 + half * 64 + 32);
            TC_WAIT_LD();
            if (slot < ne) {
                float* o = out + (size_t)tok * HIDDEN + col0 + blk * 128 + half * 64;
#pragma unroll
                for (int c = 0; c < 32; c++) atomicAdd(o + c, w * __uint_as_float(d0[c]));
#pragma unroll
                for (int c = 0; c < 32; c++) atomicAdd(o + 32 + c, w * __uint_as_float(d1[c]));
            }
        }
    }
    __syncthreads();
    if (warp == 0) TC_DEALLOC(tmem, 256);
}

// =================================================================
// cp.async fallback GEMMs — round-9 kernels (known-good path)
// =================================================================
template <int NS, typename BRowOf>
__device__ __forceinline__ void mma_mainloop(
    uint32_t smA_u, uint32_t smB_u,
    const float* aBase, size_t aStride,
    uint32_t tmem, const uint32_t* mb, BRowOf&& bRowOf)
{
    const int tid = threadIdx.x, warp = tid >> 5;

    auto fill = [&](int st) {
        uint32_t dA = smA_u + (st % 3) * TILE_BYTES;
        uint32_t dB = smB_u + (st % 3) * TILE_BYTES;
#pragma unroll
        for (int j = 0; j < 4; j++) {
            int i = tid + NTH * j;
            int row = i >> 3, c = i & 7;
            uint32_t so = swz((uint32_t)(row * 128 + c * 16));
            cp16(dA + so, aBase + (size_t)row * aStride + st * BK + c * 4);
            cp16(dB + so, bRowOf(row) + st * BK + c * 4);
        }
        cp_commit();
    };

    fill(0); fill(1);

    for (int s = 0; s < NS; s++) {
        if (s < NS - 1) cp_wait<1>();
        else            cp_wait<0>();
        FENCE_ASYNC();
        __syncthreads();

        if (warp == 0 && elect_one()) {
            uint64_t ad = mkdesc(smA_u + (s % 3) * TILE_BYTES);
            uint64_t bd = mkdesc(smB_u + (s % 3) * TILE_BYTES);
#pragma unroll
            for (int k = 0; k < 4; k++)
                mma_ss_tf32(tmem, ad + 2 * k, bd + 2 * k, MMA_IDESC, !(s == 0 && k == 0));
            TC_COMMIT(mb[s % 3]);
        }

        if (s + 2 < NS) {
            if (s >= 1) MBAR_WAIT(mb[(s - 1) % 3], (((s - 1) / 3) & 1));
            fill(s + 2);
        }
    }
    MBAR_WAIT(mb[(NS - 1) % 3], (((NS - 1) / 3) & 1));
    TC_FENCE_AFTER();
}

__global__ void __launch_bounds__(NTH, 2)
gemm1_kernel(const float* __restrict__ W13) {
    const int e = blockIdx.z;
    const int ne = g_count[e];
    const int row0 = blockIdx.y * 128;
    if (row0 >= ne) return;
    const int col0 = blockIdx.x * 64;

    extern __shared__ char dynsm[];
    __shared__ uint32_t s_tmem;
    __shared__ __align__(8) uint64_t s_mbar[3];
    __shared__ uint32_t s_mb[3];

    char* smA_c = (char*)(((uintptr_t)dynsm + 1023) & ~(uintptr_t)1023);
    const uint32_t smA_u = smem_u32(smA_c);
    const uint32_t smB_u = smA_u + 3 * TILE_BYTES;

    const int tid = threadIdx.x, warp = tid >> 5, lane = tid & 31;
    if (tid < 3) { MBAR_INIT(smem_u32(&s_mbar[tid]), 1); s_mb[tid] = smem_u32(&s_mbar[tid]); }
    if (warp == 0) { TC_ALLOC(smem_u32(&s_tmem), 128); TC_RELINQ(); }
    __syncthreads();
    const uint32_t tmem = s_tmem;

    const float* aBase = g_xg + ((size_t)e * TOKENS + row0) * HIDDEN;
    const float* wBase = W13 + (size_t)e * (2 * INTER) * HIDDEN;

    auto bRowOf = [&](int row) -> const float* {
        int grow = (row < 64) ? (col0 + row) : (INTER + col0 + row - 64);
        return wBase + (size_t)grow * HIDDEN;
    };

    mma_mainloop<HIDDEN / BK>(smA_u, smB_u, aBase, HIDDEN, tmem, s_mb, bRowOf);

    {
        const int sub = warp & 3, half = warp >> 2;
        uint32_t gr[32], ur[32];
        TC_LD_X32(gr, tmem + 32 * half);
        TC_LD_X32(ur, tmem + 64 + 32 * half);
        TC_WAIT_LD();
        const int slot = row0 + sub * 32 + lane;
        if (slot < ne) {
            float* dst = g_act + ((size_t)e * TOKENS + slot) * INTER + col0 + 32 * half;
#pragma unroll
            for (int c = 0; c < 32; c += 4) {
                float4 ov;
#pragma unroll
                for (int q = 0; q < 4; q++) {
                    float gg = __uint_as_float(gr[c + q]) * SCALE;
                    float uu = __uint_as_float(ur[c + q]) * SCALE;
                    (&ov.x)[q] = rtf(gg / (1.f + __expf(-gg)) * uu);
                }
                *reinterpret_cast<float4*>(dst + c) = ov;
            }
        }
    }
    __syncthreads();
    if (warp == 0) TC_DEALLOC(tmem, 128);
}

__global__ void __launch_bounds__(NTH, 2)
gemm2_kernel(const float* __restrict__ W2, float* __restrict__ out) {
    const int e  = blockIdx.z >> 1;
    const int ks = blockIdx.z & 1;
    const int ne = g_count[e];
    const int row0 = blockIdx.y * 128;
    if (row0 >= ne) return;
    const int col0 = blockIdx.x * 128;
    const int kbase = ks * (INTER / 2);

    extern __shared__ char dynsm[];
    __shared__ uint32_t s_tmem;
    __shared__ __align__(8) uint64_t s_mbar[3];
    __shared__ uint32_t s_mb[3];

    char* smA_c = (char*)(((uintptr_t)dynsm + 1023) & ~(uintptr_t)1023);
    const uint32_t smA_u = smem_u32(smA_c);
    const uint32_t smB_u = smA_u + 3 * TILE_BYTES;

    const int tid = threadIdx.x, warp = tid >> 5, lane = tid & 31;
    if (tid < 3) { MBAR_INIT(smem_u32(&s_mbar[tid]), 1); s_mb[tid] = smem_u32(&s_mbar[tid]); }
    if (warp == 0) { TC_ALLOC(smem_u32(&s_tmem), 128); TC_RELINQ(); }
    __syncthreads();
    const uint32_t tmem = s_tmem;

    const float* aBase = g_act + ((size_t)e * TOKENS + row0) * INTER + kbase;
    const float* bBase = W2 + (size_t)e * HIDDEN * INTER + kbase;

    auto bRowOf = [&](int row) -> const float* {
        return bBase + (size_t)(col0 + row) * INTER;
    };

    mma_mainloop<(INTER / 2) / BK>(smA_u, smB_u, aBase, INTER, tmem, s_mb, bRowOf);

    {
        const int sub = warp & 3, half = warp >> 2;
        uint32_t d0[32], d1[32];
        TC_LD_X32(d0, tmem + 64 * half);
        TC_LD_X32(d1, tmem + 64 * half + 32);
        TC_WAIT_LD();
        const int slot = row0 + sub * 32 + lane;
        if (slot < ne) {
            const int tok = g_tok[e][slot];
            const float w = g_w[e][slot] * SCALE;
            float* o = out + (size_t)tok * HIDDEN + col0 + 64 * half;
#pragma unroll
            for (int c = 0; c < 32; c++) atomicAdd(o + c, w * __uint_as_float(d0[c]));
#pragma unroll
            for (int c = 0; c < 32; c++) atomicAdd(o + 32 + c, w * __uint_as_float(d1[c]));
        }
    }
    __syncthreads();
    if (warp == 0) TC_DEALLOC(tmem, 128);
}

#else
// =================================================================
// Fallback (compute_103 PTX pass only; never executes on sm_103a device)
// =================================================================
__device__ __forceinline__ float trunc_tf32(float f) {
    return __uint_as_float(__float_as_uint(f) & 0xFFFFE000u);
}

__global__ void __launch_bounds__(NTH, 2)
gemm1_kernel(const float* __restrict__ W13) {
    const int e = blockIdx.z;
    const int ne = g_count[e];
    const int row0 = blockIdx.y * 128;
    if (row0 >= ne) return;
    const int col0 = blockIdx.x * 64;
    const float* wBase = W13 + (size_t)e * (2 * INTER) * HIDDEN;

    for (int idx = threadIdx.x; idx < 128 * 64; idx += NTH) {
        int rr = idx >> 6, cc = idx & 63;
        int slot = row0 + rr;
        if (slot >= ne) continue;
        const float* a = g_xg + ((size_t)e * TOKENS + slot) * HIDDEN;
        const float* bg = wBase + (size_t)(col0 + cc) * HIDDEN;
        const float* bu = wBase + (size_t)(INTER + col0 + cc) * HIDDEN;
        float sg = 0.f, su = 0.f;
        for (int k = 0; k < HIDDEN; k++) {
            float av = a[k];
            sg += av * trunc_tf32(bg[k]);
            su += av * trunc_tf32(bu[k]);
        }
        sg *= SCALE; su *= SCALE;
        float act = sg / (1.f + __expf(-sg)) * su;
        g_act[((size_t)e * TOKENS + slot) * INTER + col0 + cc] = rtf(act);
    }
}

__global__ void __launch_bounds__(NTH, 2)
gemm2_kernel(const float* __restrict__ W2, float* __restrict__ out) {
    const int e  = blockIdx.z >> 1;
    const int ks = blockIdx.z & 1;
    const int ne = g_count[e];
    const int row0 = blockIdx.y * 128;
    if (row0 >= ne) return;
    const int col0 = blockIdx.x * 128;
    const int kbase = ks * (INTER / 2);
    const float* bBase = W2 + (size_t)e * HIDDEN * INTER;

    for (int idx = threadIdx.x; idx < 128 * 128; idx += NTH) {
        int rr = idx >> 7, cc = idx & 127;
        int slot = row0 + rr;
        if (slot >= ne) continue;
        const float* a = g_act + ((size_t)e * TOKENS + slot) * INTER + kbase;
        const float* b = bBase + (size_t)(col0 + cc) * INTER + kbase;
        float s = 0.f;
        for (int k = 0; k < INTER / 2; k++) s += a[k] * trunc_tf32(b[k]);
        atomicAdd(&out[(size_t)g_tok[e][slot] * HIDDEN + col0 + cc],
                  g_w[e][slot] * SCALE * s);
    }
}

__global__ void __launch_bounds__(NTH, 2)
gemm1_tma_kernel(const __grid_constant__ CUtensorMap mapA,
                 const __grid_constant__ CUtensorMap mapB) {}
__global__ void __launch_bounds__(NTH, 2)
gemm2_tma_kernel(const __grid_constant__ CUtensorMap mapA,
                 const __grid_constant__ CUtensorMap mapB,
                 float* __restrict__ out) {}
#endif  // USE_TC

// ---------------- host: tensormap construction via dlopen ----------------
typedef CUresult (*EncodeTiledFn)(
    CUtensorMap*, CUtensorMapDataType, cuuint32_t, void*,
    const cuuint64_t*, const cuuint64_t*, const cuuint32_t*, const cuuint32_t*,
    CUtensorMapInterleave, CUtensorMapSwizzle, CUtensorMapL2promotion,
    CUtensorMapFloatOOBfill);

static bool make_map2d(EncodeTiledFn fn, CUtensorMap* m, void* base,
                       uint64_t width, uint64_t height, uint32_t box0, uint32_t box1) {
    cuuint64_t dims[2] = {width, height};
    cuuint64_t strides[1] = {width * sizeof(float)};
    cuuint32_t box[2] = {box0, box1};
    cuuint32_t elemstr[2] = {1, 1};
    CUresult r = fn(m, CU_TENSOR_MAP_DATA_TYPE_FLOAT32, 2, base,
                    dims, strides, box, elemstr,
                    CU_TENSOR_MAP_INTERLEAVE_NONE, CU_TENSOR_MAP_SWIZZLE_128B,
                    CU_TENSOR_MAP_L2_PROMOTION_L2_128B,
                    CU_TENSOR_MAP_FLOAT_OOB_FILL_NONE);
    return r == CUDA_SUCCESS;
}

// ---------------- launch ----------------
extern "C" void kernel_launch(void* const* d_in, const int* in_sizes, int n_in,
                              void* d_out, int out_size) {
    const float* X      = (const float*)d_in[0];
    const float* logits = (const float*)d_in[1];
    const float* W13    = (const float*)d_in[2];
    const float* W2     = (const float*)d_in[3];
    float* out = (float*)d_out;

    cudaFuncSetAttribute(gemm1_kernel, cudaFuncAttributeMaxDynamicSharedMemorySize, DYN_SMEM);
    cudaFuncSetAttribute(gemm2_kernel, cudaFuncAttributeMaxDynamicSharedMemorySize, DYN_SMEM);
    cudaFuncSetAttribute(gemm1_tma_kernel, cudaFuncAttributeMaxDynamicSharedMemorySize, DYN_SMEM);
    cudaFuncSetAttribute(gemm2_tma_kernel, cudaFuncAttributeMaxDynamicSharedMemorySize, DYN_SMEM);

    bool tma_ok = false;
    CUtensorMap mA1, mB1, mA2, mB2;
    {
        void* h = dlopen("libcuda.so.1", RTLD_NOW | RTLD_GLOBAL);
        if (!h) h = dlopen("libcuda.so", RTLD_NOW | RTLD_GLOBAL);
        EncodeTiledFn fn = h ? (EncodeTiledFn)dlsym(h, "cuTensorMapEncodeTiled") : nullptr;
        void *p_xg = nullptr, *p_act = nullptr;
        if (fn &&
            cudaGetSymbolAddress(&p_xg, g_xg) == cudaSuccess &&
            cudaGetSymbolAddress(&p_act, g_act) == cudaSuccess) {
            tma_ok =
                make_map2d(fn, &mA1, p_xg,        HIDDEN, (uint64_t)NEXP * TOKENS,     32, 128) &&
                make_map2d(fn, &mB1, (void*)W13,  HIDDEN, (uint64_t)NEXP * 2 * INTER,  32, 128) &&
                make_map2d(fn, &mA2, p_act,       INTER,  (uint64_t)NEXP * TOKENS,     32, 128) &&
                make_map2d(fn, &mB2, (void*)W2,   INTER,  (uint64_t)NEXP * HIDDEN,     32, 128);
        }
    }

    zero_kernel<<<(TOKENS * HIDDEN / 4) / 256, 256>>>(out);
    router_kernel<<<(TOKENS + 255) / 256, 256>>>(logits);

    dim3 gg(TOKENS, NEXP);
    gather_kernel<<<gg, 256>>>(X);

    if (tma_ok) {
        dim3 g1(INTER / 128, TOKENS / 128, NEXP);          // BM=128, BN=256 (g+u)
        dim3 g2(HIDDEN / 256, TOKENS / 128, NEXP * 2);     // BM=128, BN=256, splitK=2
        gemm1_tma_kernel<<<g1, NTH, DYN_SMEM>>>(mA1, mB1);
        gemm2_tma_kernel<<<g2, NTH, DYN_SMEM>>>(mA2, mB2, out);
    } else {
        dim3 g1(INTER / 64, TOKENS / 128, NEXP);
        dim3 g2(HIDDEN / 128, TOKENS / 128, NEXP * 2);
        gemm1_kernel<<<g1, NTH, DYN_SMEM>>>(W13);
        gemm2_kernel<<<g2, NTH, DYN_SMEM>>>(W2, out);
    }
}